// round 1
// baseline (speedup 1.0000x reference)
#include <cuda_runtime.h>
#include <math.h>
#include <stdint.h>

#define QL   1024
#define KVL  1024
#define BB   8
#define DM   1024
#define NH   16
#define DH   64
#define ROWS (QL*BB)     // 8192
#define NDH  (NH*DH)     // 1024

// ---------------- scratch (device globals: no allocations allowed) ----------------
__device__ __align__(16) float g_hln[ROWS*DM];          // LN(h), also residual
__device__ __align__(16) float g_q[BB*NH*QL*DH];        // [b*16+n][i][dh], pre-scaled by 1/8
__device__ __align__(16) float g_k[BB*NH*KVL*DH];       // [b*16+n][j][dh]
__device__ __align__(16) float g_v[BB*NH*KVL*DH];       // [b*16+n][j][dh]
__device__ __align__(16) float g_attn[ROWS*NDH];        // [i*8+b][n*64+dh]
__device__ int g_mask[KVL*BB];                          // 1 = masked

// ---------------- mask dtype detection + canonicalization ----------------
// Supports mask serialized as int32/float32 (4B words 0/1 or 0/1.0f) or bool/int8 (bytes 0/1).
__global__ void mask_kernel(const unsigned int* __restrict__ mw,
                            const unsigned char* __restrict__ mb) {
    __shared__ int s_w01, s_f01;
    int t = threadIdx.x;
    if (t == 0) { s_w01 = 1; s_f01 = 1; }
    __syncthreads();
    int w01 = 1, f01 = 1;
    // 2048 words = 8192 bytes: safe to read for every candidate dtype
    for (int i = t; i < 2048; i += 256) {
        unsigned int w = mw[i];
        if (w > 1u) w01 = 0;
        if (w != 0u && w != 0x3F800000u) f01 = 0;
    }
    if (!w01) atomicAnd(&s_w01, 0);
    if (!f01) atomicAnd(&s_f01, 0);
    __syncthreads();
    bool word_mode = (s_w01 != 0) || (s_f01 != 0);
    for (int e = t; e < KVL*BB; e += 256) {
        int v = word_mode ? (mw[e] != 0u) : (mb[e] != 0);
        g_mask[e] = v;
    }
}

// ---------------- layernorm: one block per row ----------------
__global__ void ln_kernel(const float* __restrict__ h,
                          const float* __restrict__ gamma,
                          const float* __restrict__ beta) {
    int row = blockIdx.x;
    int t = threadIdx.x;
    const float4* hp = reinterpret_cast<const float4*>(h + (size_t)row * DM);
    float4 x = hp[t];
    float s  = x.x + x.y + x.z + x.w;
    float ss = x.x*x.x + x.y*x.y + x.z*x.z + x.w*x.w;
    #pragma unroll
    for (int off = 16; off; off >>= 1) {
        s  += __shfl_xor_sync(0xffffffffu, s,  off);
        ss += __shfl_xor_sync(0xffffffffu, ss, off);
    }
    __shared__ float sh_s[8], sh_ss[8];
    __shared__ float s_mu, s_rstd;
    if ((t & 31) == 0) { sh_s[t >> 5] = s; sh_ss[t >> 5] = ss; }
    __syncthreads();
    if (t == 0) {
        float S = 0.f, SS = 0.f;
        #pragma unroll
        for (int i = 0; i < 8; i++) { S += sh_s[i]; SS += sh_ss[i]; }
        float mu  = S / DM;
        float var = SS / DM - mu * mu;
        s_mu = mu;
        s_rstd = rsqrtf(var + 1e-5f);
    }
    __syncthreads();
    float mu = s_mu, r = s_rstd;
    const float4* gp = reinterpret_cast<const float4*>(gamma);
    const float4* bp = reinterpret_cast<const float4*>(beta);
    float4 g = gp[t], bt = bp[t];
    float4 o;
    o.x = (x.x - mu) * r * g.x + bt.x;
    o.y = (x.y - mu) * r * g.y + bt.y;
    o.z = (x.z - mu) * r * g.z + bt.z;
    o.w = (x.w - mu) * r * g.w + bt.w;
    reinterpret_cast<float4*>(g_hln + (size_t)row * DM)[t] = o;
}

// ---------------- tiled fp32 SGEMM: 128x128x32, 256 thr, 8x8 microtile ----------------
// MODE 0: C = g_hln @ Wq  -> scatter into g_q (scaled by 0.125)
// MODE 1: C = c     @ Wkv -> scatter into g_k / g_v
// MODE 2: C = g_attn@ Wo  -> out = g_hln + C
template<int MODE>
__global__ void sgemm(const float* __restrict__ Aopt,
                      const float* __restrict__ W,
                      float* __restrict__ out, int K, int N) {
    __shared__ float As[32][132];   // k-major: As[k][m]
    __shared__ float Bs[32][132];   // Bs[k][n]
    const float* A = (MODE == 0) ? g_hln : (MODE == 2) ? g_attn : Aopt;

    int t  = threadIdx.x;
    int tx = t & 15, ty = t >> 4;
    int m0 = blockIdx.y * 128, n0 = blockIdx.x * 128;

    float acc[8][8];
    #pragma unroll
    for (int i = 0; i < 8; i++)
        #pragma unroll
        for (int j = 0; j < 8; j++) acc[i][j] = 0.f;

    for (int kt = 0; kt < K; kt += 32) {
        #pragma unroll
        for (int e = 0; e < 4; e++) {
            int lin = e * 256 + t;
            int row = lin >> 3, c4 = lin & 7;   // A tile: 128 rows x 8 float4
            float4 v = *reinterpret_cast<const float4*>(&A[(size_t)(m0 + row) * K + kt + c4 * 4]);
            As[c4 * 4 + 0][row] = v.x;
            As[c4 * 4 + 1][row] = v.y;
            As[c4 * 4 + 2][row] = v.z;
            As[c4 * 4 + 3][row] = v.w;
            int rb = lin >> 5, cb = lin & 31;   // B tile: 32 rows x 32 float4
            float4 w = *reinterpret_cast<const float4*>(&W[(size_t)(kt + rb) * N + n0 + cb * 4]);
            *reinterpret_cast<float4*>(&Bs[rb][cb * 4]) = w;
        }
        __syncthreads();
        #pragma unroll
        for (int k = 0; k < 32; k++) {
            float4 a0 = *reinterpret_cast<float4*>(&As[k][ty * 4]);
            float4 a1 = *reinterpret_cast<float4*>(&As[k][64 + ty * 4]);
            float4 b0 = *reinterpret_cast<float4*>(&Bs[k][tx * 4]);
            float4 b1 = *reinterpret_cast<float4*>(&Bs[k][64 + tx * 4]);
            float a[8] = {a0.x, a0.y, a0.z, a0.w, a1.x, a1.y, a1.z, a1.w};
            float b[8] = {b0.x, b0.y, b0.z, b0.w, b1.x, b1.y, b1.z, b1.w};
            #pragma unroll
            for (int i = 0; i < 8; i++)
                #pragma unroll
                for (int j = 0; j < 8; j++) acc[i][j] += a[i] * b[j];
        }
        __syncthreads();
    }

    #pragma unroll
    for (int i = 0; i < 8; i++) {
        int r = m0 + ((i < 4) ? (ty * 4 + i) : (64 + ty * 4 + i - 4));
        #pragma unroll
        for (int j = 0; j < 8; j++) {
            int c = n0 + ((j < 4) ? (tx * 4 + j) : (64 + tx * 4 + j - 4));
            float val = acc[i][j];
            if (MODE == 0) {
                int ii = r >> 3, b = r & 7, n = c >> 6, dh = c & 63;
                g_q[(((size_t)(b * NH + n)) * QL + ii) * DH + dh] = val * 0.125f;
            } else if (MODE == 1) {
                int jj = r >> 3, b = r & 7;
                if (c < NDH) {
                    int n = c >> 6, dh = c & 63;
                    g_k[(((size_t)(b * NH + n)) * KVL + jj) * DH + dh] = val;
                } else {
                    int c2 = c - NDH;
                    int n = c2 >> 6, dh = c2 & 63;
                    g_v[(((size_t)(b * NH + n)) * KVL + jj) * DH + dh] = val;
                }
            } else {
                out[(size_t)r * DM + c] = g_hln[(size_t)r * DM + c] + val;
            }
        }
    }
}

// ---------------- flash attention: grid(16 i-tiles, 128 bn), 256 thr ----------------
// smem: Qs[k][i], Ks[k][j] (d-major), Vs[j][d], Ps[r][j], stride 68 floats
#define AST 68
__global__ void attn_kernel() {
    extern __shared__ float sm[];
    float* Qs = sm;
    float* Ks = sm + 64 * AST;
    float* Vs = sm + 2 * 64 * AST;
    float* Ps = sm + 3 * 64 * AST;

    int t  = threadIdx.x;
    int tx = t & 15, ty = t >> 4;
    int i0 = blockIdx.x * 64;
    int bn = blockIdx.y;
    int b  = bn >> 4, n = bn & 15;

    const float* Qg = g_q + (size_t)bn * QL * DH;
    const float* Kg = g_k + (size_t)bn * KVL * DH;
    const float* Vg = g_v + (size_t)bn * KVL * DH;

    // load Q tile transposed: Qs[d][i]
    #pragma unroll
    for (int e = 0; e < 4; e++) {
        int lin = e * 256 + t;
        int row = lin >> 4, d4 = lin & 15;
        float4 v = *reinterpret_cast<const float4*>(&Qg[(size_t)(i0 + row) * DH + d4 * 4]);
        Qs[(d4 * 4 + 0) * AST + row] = v.x;
        Qs[(d4 * 4 + 1) * AST + row] = v.y;
        Qs[(d4 * 4 + 2) * AST + row] = v.z;
        Qs[(d4 * 4 + 3) * AST + row] = v.w;
    }

    float m_[4], l_[4], o_[4][4];
    #pragma unroll
    for (int i = 0; i < 4; i++) {
        m_[i] = -1e30f; l_[i] = 0.f;
        #pragma unroll
        for (int j = 0; j < 4; j++) o_[i][j] = 0.f;
    }

    for (int jt = 0; jt < 16; jt++) {
        int j0 = jt * 64;
        __syncthreads();   // prev iter's GEMM2 reads done (and Qs visible on iter 0 via next sync)
        #pragma unroll
        for (int e = 0; e < 4; e++) {
            int lin = e * 256 + t;
            int row = lin >> 4, d4 = lin & 15;
            float4 kv = *reinterpret_cast<const float4*>(&Kg[(size_t)(j0 + row) * DH + d4 * 4]);
            Ks[(d4 * 4 + 0) * AST + row] = kv.x;
            Ks[(d4 * 4 + 1) * AST + row] = kv.y;
            Ks[(d4 * 4 + 2) * AST + row] = kv.z;
            Ks[(d4 * 4 + 3) * AST + row] = kv.w;
            float4 vv = *reinterpret_cast<const float4*>(&Vg[(size_t)(j0 + row) * DH + d4 * 4]);
            *reinterpret_cast<float4*>(&Vs[row * AST + d4 * 4]) = vv;
        }
        __syncthreads();

        // S = Q K^T (Q already scaled by 1/sqrt(64))
        float s[4][4];
        #pragma unroll
        for (int i = 0; i < 4; i++)
            #pragma unroll
            for (int j = 0; j < 4; j++) s[i][j] = 0.f;
        #pragma unroll
        for (int k = 0; k < 64; k++) {
            float4 a  = *reinterpret_cast<float4*>(&Qs[k * AST + ty * 4]);
            float4 bq = *reinterpret_cast<float4*>(&Ks[k * AST + tx * 4]);
            float av[4] = {a.x, a.y, a.z, a.w};
            float bv[4] = {bq.x, bq.y, bq.z, bq.w};
            #pragma unroll
            for (int i = 0; i < 4; i++)
                #pragma unroll
                for (int j = 0; j < 4; j++) s[i][j] += av[i] * bv[j];
        }
        // mask: replace with -10000 exactly (matches jnp.where)
        #pragma unroll
        for (int j = 0; j < 4; j++) {
            int jg = j0 + tx * 4 + j;
            if (g_mask[jg * BB + b]) {
                s[0][j] = -1e4f; s[1][j] = -1e4f; s[2][j] = -1e4f; s[3][j] = -1e4f;
            }
        }
        // online softmax per row (row group = 16 lanes sharing ty)
        #pragma unroll
        for (int i = 0; i < 4; i++) {
            float mx = fmaxf(fmaxf(s[i][0], s[i][1]), fmaxf(s[i][2], s[i][3]));
            #pragma unroll
            for (int off = 8; off; off >>= 1)
                mx = fmaxf(mx, __shfl_xor_sync(0xffffffffu, mx, off));
            float mn = fmaxf(m_[i], mx);
            float scale = __expf(m_[i] - mn);
            float ps = 0.f;
            #pragma unroll
            for (int j = 0; j < 4; j++) {
                float p = __expf(s[i][j] - mn);
                s[i][j] = p;
                ps += p;
            }
            #pragma unroll
            for (int off = 8; off; off >>= 1)
                ps += __shfl_xor_sync(0xffffffffu, ps, off);
            l_[i] = l_[i] * scale + ps;
            #pragma unroll
            for (int j = 0; j < 4; j++) o_[i][j] *= scale;
            m_[i] = mn;
            #pragma unroll
            for (int j = 0; j < 4; j++)
                Ps[(ty * 4 + i) * AST + tx * 4 + j] = s[i][j];
        }
        __syncthreads();
        // O += P V
        #pragma unroll
        for (int j = 0; j < 64; j++) {
            float4 v = *reinterpret_cast<float4*>(&Vs[j * AST + tx * 4]);
            float p0 = Ps[(ty * 4 + 0) * AST + j];
            float p1 = Ps[(ty * 4 + 1) * AST + j];
            float p2 = Ps[(ty * 4 + 2) * AST + j];
            float p3 = Ps[(ty * 4 + 3) * AST + j];
            o_[0][0] += p0 * v.x; o_[0][1] += p0 * v.y; o_[0][2] += p0 * v.z; o_[0][3] += p0 * v.w;
            o_[1][0] += p1 * v.x; o_[1][1] += p1 * v.y; o_[1][2] += p1 * v.z; o_[1][3] += p1 * v.w;
            o_[2][0] += p2 * v.x; o_[2][1] += p2 * v.y; o_[2][2] += p2 * v.z; o_[2][3] += p2 * v.w;
            o_[3][0] += p3 * v.x; o_[3][1] += p3 * v.y; o_[3][2] += p3 * v.z; o_[3][3] += p3 * v.w;
        }
    }

    #pragma unroll
    for (int i = 0; i < 4; i++) {
        int ig = i0 + ty * 4 + i;
        float inv = 1.0f / l_[i];
        float4 ov;
        ov.x = o_[i][0] * inv;
        ov.y = o_[i][1] * inv;
        ov.z = o_[i][2] * inv;
        ov.w = o_[i][3] * inv;
        size_t base = ((size_t)ig * BB + b) * NDH + n * DH + tx * 4;
        *reinterpret_cast<float4*>(&g_attn[base]) = ov;
    }
}

// ---------------- launch ----------------
extern "C" void kernel_launch(void* const* d_in, const int* in_sizes, int n_in,
                              void* d_out, int out_size) {
    const float* h     = (const float*)d_in[0];
    const float* c     = (const float*)d_in[1];
    const void*  mask  = d_in[2];
    const float* Wq    = (const float*)d_in[3];
    const float* Wkv   = (const float*)d_in[4];
    const float* Wo    = (const float*)d_in[5];
    const float* gamma = (const float*)d_in[6];
    const float* beta  = (const float*)d_in[7];
    float* out = (float*)d_out;

    // Opt-in smem for attention (69,632 B). Ignore return: on the (uncaptured)
    // correctness call it succeeds; the attribute persists for later calls.
    (void)cudaFuncSetAttribute(attn_kernel, cudaFuncAttributeMaxDynamicSharedMemorySize, 69632);

    mask_kernel<<<1, 256>>>((const unsigned int*)mask, (const unsigned char*)mask);
    ln_kernel<<<ROWS, 256>>>(h, gamma, beta);
    sgemm<1><<<dim3(16, 64), 256>>>(c, Wkv, nullptr, DM, 2 * NDH);   // K,V proj
    sgemm<0><<<dim3(8, 64), 256>>>(nullptr, Wq, nullptr, DM, NDH);   // Q proj
    attn_kernel<<<dim3(16, 128), 256, 69632>>>();
    sgemm<2><<<dim3(8, 64), 256>>>(nullptr, Wo, out, NDH, DM);       // O proj + residual
}

// round 3
// speedup vs baseline: 2.0768x; 2.0768x over previous
#include <cuda_runtime.h>
#include <cuda_bf16.h>
#include <math.h>
#include <stdint.h>

#define QL   1024
#define KVL  1024
#define BB   8
#define DM   1024
#define NH   16
#define DH   64
#define ROWS (QL*BB)     // 8192
#define NDH  (NH*DH)     // 1024

// ---------------- scratch (device globals: no allocations allowed) ----------------
__device__ __align__(16) float g_hln[ROWS*DM];            // LN(h) fp32 (GEMM A + residual)
__device__ __align__(16) __nv_bfloat16 g_q_h[BB*NH*QL*DH];
__device__ __align__(16) __nv_bfloat16 g_q_l[BB*NH*QL*DH];
__device__ __align__(16) __nv_bfloat16 g_k_h[BB*NH*KVL*DH];
__device__ __align__(16) __nv_bfloat16 g_k_l[BB*NH*KVL*DH];
__device__ __align__(16) __nv_bfloat16 g_v_h[BB*NH*KVL*DH];
__device__ __align__(16) __nv_bfloat16 g_v_l[BB*NH*KVL*DH];
__device__ __align__(16) float g_attn[ROWS*NDH];          // attention output fp32
__device__ int g_mask[KVL*BB];                            // 1 = masked

// ---------------- small helpers ----------------
__device__ __forceinline__ void ldsm4(uint32_t &r0, uint32_t &r1, uint32_t &r2, uint32_t &r3,
                                      const void* p) {
    uint32_t a = (uint32_t)__cvta_generic_to_shared(p);
    asm volatile("ldmatrix.sync.aligned.m8n8.x4.shared.b16 {%0,%1,%2,%3},[%4];\n"
                 : "=r"(r0), "=r"(r1), "=r"(r2), "=r"(r3) : "r"(a));
}
__device__ __forceinline__ void ldsm4t(uint32_t &r0, uint32_t &r1, uint32_t &r2, uint32_t &r3,
                                       const void* p) {
    uint32_t a = (uint32_t)__cvta_generic_to_shared(p);
    asm volatile("ldmatrix.sync.aligned.m8n8.x4.trans.shared.b16 {%0,%1,%2,%3},[%4];\n"
                 : "=r"(r0), "=r"(r1), "=r"(r2), "=r"(r3) : "r"(a));
}
__device__ __forceinline__ void mma_bf16(float &c0, float &c1, float &c2, float &c3,
                                         uint32_t a0, uint32_t a1, uint32_t a2, uint32_t a3,
                                         uint32_t b0, uint32_t b1) {
    asm volatile(
        "mma.sync.aligned.m16n8k16.row.col.f32.bf16.bf16.f32 "
        "{%0,%1,%2,%3},{%4,%5,%6,%7},{%8,%9},{%0,%1,%2,%3};\n"
        : "+f"(c0), "+f"(c1), "+f"(c2), "+f"(c3)
        : "r"(a0), "r"(a1), "r"(a2), "r"(a3), "r"(b0), "r"(b1));
}
__device__ __forceinline__ uint32_t packbf(__nv_bfloat16 x, __nv_bfloat16 y) {
    return ((uint32_t)__bfloat16_as_ushort(y) << 16) | (uint32_t)__bfloat16_as_ushort(x);
}
// split pair of floats into (hi,hi) and (lo,lo) packed bf16x2
__device__ __forceinline__ void split2(float x, float y, uint32_t &hi, uint32_t &lo) {
    __nv_bfloat16 hx = __float2bfloat16_rn(x), hy = __float2bfloat16_rn(y);
    __nv_bfloat16 lx = __float2bfloat16_rn(x - __bfloat162float(hx));
    __nv_bfloat16 ly = __float2bfloat16_rn(y - __bfloat162float(hy));
    hi = packbf(hx, hy);
    lo = packbf(lx, ly);
}

// ---------------- mask dtype detection + canonicalization ----------------
__global__ void mask_kernel(const unsigned int* __restrict__ mw,
                            const unsigned char* __restrict__ mb) {
    __shared__ int s_w01, s_f01;
    int t = threadIdx.x;
    if (t == 0) { s_w01 = 1; s_f01 = 1; }
    __syncthreads();
    int w01 = 1, f01 = 1;
    for (int i = t; i < 2048; i += 256) {
        unsigned int w = mw[i];
        if (w > 1u) w01 = 0;
        if (w != 0u && w != 0x3F800000u) f01 = 0;
    }
    if (!w01) atomicAnd(&s_w01, 0);
    if (!f01) atomicAnd(&s_f01, 0);
    __syncthreads();
    bool word_mode = (s_w01 != 0) || (s_f01 != 0);
    for (int e = t; e < KVL*BB; e += 256) {
        int v = word_mode ? (mw[e] != 0u) : (mb[e] != 0);
        g_mask[e] = v;
    }
}

// ---------------- layernorm: one block per row ----------------
__global__ void ln_kernel(const float* __restrict__ h,
                          const float* __restrict__ gamma,
                          const float* __restrict__ beta) {
    int row = blockIdx.x;
    int t = threadIdx.x;
    const float4* hp = reinterpret_cast<const float4*>(h + (size_t)row * DM);
    float4 x = hp[t];
    float s  = x.x + x.y + x.z + x.w;
    float ss = x.x*x.x + x.y*x.y + x.z*x.z + x.w*x.w;
    #pragma unroll
    for (int off = 16; off; off >>= 1) {
        s  += __shfl_xor_sync(0xffffffffu, s,  off);
        ss += __shfl_xor_sync(0xffffffffu, ss, off);
    }
    __shared__ float sh_s[8], sh_ss[8];
    __shared__ float s_mu, s_rstd;
    if ((t & 31) == 0) { sh_s[t >> 5] = s; sh_ss[t >> 5] = ss; }
    __syncthreads();
    if (t == 0) {
        float S = 0.f, SS = 0.f;
        #pragma unroll
        for (int i = 0; i < 8; i++) { S += sh_s[i]; SS += sh_ss[i]; }
        float mu  = S / DM;
        float var = SS / DM - mu * mu;
        s_mu = mu;
        s_rstd = rsqrtf(var + 1e-5f);
    }
    __syncthreads();
    float mu = s_mu, r = s_rstd;
    const float4* gp = reinterpret_cast<const float4*>(gamma);
    const float4* bp = reinterpret_cast<const float4*>(beta);
    float4 g = gp[t], bt = bp[t];
    float4 o;
    o.x = (x.x - mu) * r * g.x + bt.x;
    o.y = (x.y - mu) * r * g.y + bt.y;
    o.z = (x.z - mu) * r * g.z + bt.z;
    o.w = (x.w - mu) * r * g.w + bt.w;
    reinterpret_cast<float4*>(g_hln + (size_t)row * DM)[t] = o;
}

// ---------------- tensor-core GEMM with bf16 split: 128x128x32, 256 thr ----------------
// MODE 0: C = g_hln @ Wq  -> q_h/q_l (scaled 0.125)
// MODE 1: C = c     @ Wkv -> k_h/l, v_h/l
// MODE 2: C = g_attn@ Wo  -> out = g_hln + C
template<int MODE>
__global__ __launch_bounds__(256)
void sgemm_mma(const float* __restrict__ Aopt, const float* __restrict__ W,
               float* __restrict__ out, int K, int N) {
    __shared__ __align__(16) __nv_bfloat16 Ah[128][40];
    __shared__ __align__(16) __nv_bfloat16 Al[128][40];
    __shared__ __align__(16) __nv_bfloat16 Bh[32][136];
    __shared__ __align__(16) __nv_bfloat16 Bl[32][136];
    const float* A = (MODE == 0) ? g_hln : (MODE == 2) ? g_attn : Aopt;

    int t = threadIdx.x;
    int lane = t & 31, wrp = t >> 5;
    int gid = lane >> 2, tig = lane & 3;
    int wm = wrp & 3, wn = wrp >> 2;              // warp tile: 32(M) x 64(N)
    int m0 = blockIdx.y * 128, n0 = blockIdx.x * 128;
    int mm = lane >> 3, mr = lane & 7;            // ldmatrix lane decomposition

    float acc[2][8][4];
    #pragma unroll
    for (int i = 0; i < 2; i++)
        #pragma unroll
        for (int f = 0; f < 8; f++)
            #pragma unroll
            for (int e = 0; e < 4; e++) acc[i][f][e] = 0.f;

    for (int kt = 0; kt < K; kt += 32) {
        #pragma unroll
        for (int e = 0; e < 4; e++) {
            int lin = e * 256 + t;
            {   // A tile: 128 rows x 8 float4
                int row = lin >> 3, c4 = lin & 7;
                float4 v = *reinterpret_cast<const float4*>(&A[(size_t)(m0 + row) * K + kt + c4 * 4]);
                uint32_t h0, l0, h1, l1;
                split2(v.x, v.y, h0, l0);
                split2(v.z, v.w, h1, l1);
                *reinterpret_cast<uint32_t*>(&Ah[row][c4 * 4])     = h0;
                *reinterpret_cast<uint32_t*>(&Ah[row][c4 * 4 + 2]) = h1;
                *reinterpret_cast<uint32_t*>(&Al[row][c4 * 4])     = l0;
                *reinterpret_cast<uint32_t*>(&Al[row][c4 * 4 + 2]) = l1;
            }
            {   // B tile: 32 rows x 32 float4
                int rb = lin >> 5, cb = lin & 31;
                float4 v = *reinterpret_cast<const float4*>(&W[(size_t)(kt + rb) * N + n0 + cb * 4]);
                uint32_t h0, l0, h1, l1;
                split2(v.x, v.y, h0, l0);
                split2(v.z, v.w, h1, l1);
                *reinterpret_cast<uint32_t*>(&Bh[rb][cb * 4])     = h0;
                *reinterpret_cast<uint32_t*>(&Bh[rb][cb * 4 + 2]) = h1;
                *reinterpret_cast<uint32_t*>(&Bl[rb][cb * 4])     = l0;
                *reinterpret_cast<uint32_t*>(&Bl[rb][cb * 4 + 2]) = l1;
            }
        }
        __syncthreads();
        #pragma unroll
        for (int kk = 0; kk < 32; kk += 16) {
            uint32_t ah[2][4], al[2][4];
            #pragma unroll
            for (int im = 0; im < 2; im++) {
                int row = 32 * wm + 16 * im + (mm & 1) * 8 + mr;
                int col = kk + (mm >> 1) * 8;
                ldsm4(ah[im][0], ah[im][1], ah[im][2], ah[im][3], &Ah[row][col]);
                ldsm4(al[im][0], al[im][1], al[im][2], al[im][3], &Al[row][col]);
            }
            uint32_t bh[8][2], bl[8][2];
            #pragma unroll
            for (int p = 0; p < 4; p++) {
                int krow = kk + (mm & 1) * 8 + mr;
                int ncol = 64 * wn + p * 16 + (mm >> 1) * 8;
                uint32_t r0, r1, r2, r3;
                ldsm4t(r0, r1, r2, r3, &Bh[krow][ncol]);
                bh[2*p][0] = r0; bh[2*p][1] = r1; bh[2*p+1][0] = r2; bh[2*p+1][1] = r3;
                ldsm4t(r0, r1, r2, r3, &Bl[krow][ncol]);
                bl[2*p][0] = r0; bl[2*p][1] = r1; bl[2*p+1][0] = r2; bl[2*p+1][1] = r3;
            }
            #pragma unroll
            for (int im = 0; im < 2; im++)
                #pragma unroll
                for (int f = 0; f < 8; f++) {
                    mma_bf16(acc[im][f][0], acc[im][f][1], acc[im][f][2], acc[im][f][3],
                             ah[im][0], ah[im][1], ah[im][2], ah[im][3], bh[f][0], bh[f][1]);
                    mma_bf16(acc[im][f][0], acc[im][f][1], acc[im][f][2], acc[im][f][3],
                             ah[im][0], ah[im][1], ah[im][2], ah[im][3], bl[f][0], bl[f][1]);
                    mma_bf16(acc[im][f][0], acc[im][f][1], acc[im][f][2], acc[im][f][3],
                             al[im][0], al[im][1], al[im][2], al[im][3], bh[f][0], bh[f][1]);
                }
        }
        __syncthreads();
    }

    // epilogue
    #pragma unroll
    for (int im = 0; im < 2; im++) {
        #pragma unroll
        for (int f = 0; f < 8; f++) {
            int cb = n0 + 64 * wn + 8 * f + 2 * tig;
            #pragma unroll
            for (int half = 0; half < 2; half++) {
                int r = m0 + 32 * wm + 16 * im + gid + half * 8;
                float v0 = acc[im][f][half * 2 + 0];
                float v1 = acc[im][f][half * 2 + 1];
                if (MODE == 0) {
                    v0 *= 0.125f; v1 *= 0.125f;
                    int ii = r >> 3, b = r & 7, n = cb >> 6, dh = cb & 63;
                    size_t base = (((size_t)(b * NH + n)) * QL + ii) * DH + dh;
                    uint32_t hp, lp;
                    split2(v0, v1, hp, lp);
                    *reinterpret_cast<uint32_t*>(&g_q_h[base]) = hp;
                    *reinterpret_cast<uint32_t*>(&g_q_l[base]) = lp;
                } else if (MODE == 1) {
                    int jj = r >> 3, b = r & 7;
                    uint32_t hp, lp;
                    split2(v0, v1, hp, lp);
                    if (cb < NDH) {
                        int n = cb >> 6, dh = cb & 63;
                        size_t base = (((size_t)(b * NH + n)) * KVL + jj) * DH + dh;
                        *reinterpret_cast<uint32_t*>(&g_k_h[base]) = hp;
                        *reinterpret_cast<uint32_t*>(&g_k_l[base]) = lp;
                    } else {
                        int c2 = cb - NDH;
                        int n = c2 >> 6, dh = c2 & 63;
                        size_t base = (((size_t)(b * NH + n)) * KVL + jj) * DH + dh;
                        *reinterpret_cast<uint32_t*>(&g_v_h[base]) = hp;
                        *reinterpret_cast<uint32_t*>(&g_v_l[base]) = lp;
                    }
                } else {
                    size_t o = (size_t)r * DM + cb;
                    out[o]     = g_hln[o]     + v0;
                    out[o + 1] = g_hln[o + 1] + v1;
                }
            }
        }
    }
}

// ---------------- flash attention with tensor cores ----------------
// grid(8 i-tiles of 128, 128 bn), 256 thr; warp w owns S rows 16w..16w+15
#define ATS 72
__global__ __launch_bounds__(256)
void attn_kernel() {
    __shared__ __align__(16) __nv_bfloat16 smt[256 * ATS];
    __shared__ int maskS[64];
    __nv_bfloat16 (*Qh)[ATS] = reinterpret_cast<__nv_bfloat16(*)[ATS]>(smt);
    __nv_bfloat16 (*Ql)[ATS] = reinterpret_cast<__nv_bfloat16(*)[ATS]>(smt + 128 * ATS);
    __nv_bfloat16 (*Kh)[ATS] = reinterpret_cast<__nv_bfloat16(*)[ATS]>(smt);
    __nv_bfloat16 (*Kl)[ATS] = reinterpret_cast<__nv_bfloat16(*)[ATS]>(smt + 64 * ATS);
    __nv_bfloat16 (*Vh)[ATS] = reinterpret_cast<__nv_bfloat16(*)[ATS]>(smt + 128 * ATS);
    __nv_bfloat16 (*Vl)[ATS] = reinterpret_cast<__nv_bfloat16(*)[ATS]>(smt + 192 * ATS);

    int t = threadIdx.x;
    int lane = t & 31, wrp = t >> 5;
    int gid = lane >> 2, tig = lane & 3;
    int mm = lane >> 3, mr = lane & 7;
    int i0 = blockIdx.x * 128;
    int bn = blockIdx.y;
    int b = bn >> 4, n = bn & 15;

    const __nv_bfloat16* Qgh = g_q_h + (size_t)bn * QL * DH;
    const __nv_bfloat16* Qgl = g_q_l + (size_t)bn * QL * DH;
    const __nv_bfloat16* Kgh = g_k_h + (size_t)bn * KVL * DH;
    const __nv_bfloat16* Kgl = g_k_l + (size_t)bn * KVL * DH;
    const __nv_bfloat16* Vgh = g_v_h + (size_t)bn * KVL * DH;
    const __nv_bfloat16* Vgl = g_v_l + (size_t)bn * KVL * DH;

    // load Q tile (128 x 64 bf16, hi+lo) then hoist fragments to registers
    #pragma unroll
    for (int e = 0; e < 4; e++) {
        int lin = e * 256 + t;
        int row = lin >> 3, c8 = lin & 7;
        *reinterpret_cast<uint4*>(&Qh[row][c8 * 8]) =
            *reinterpret_cast<const uint4*>(&Qgh[(size_t)(i0 + row) * DH + c8 * 8]);
        *reinterpret_cast<uint4*>(&Ql[row][c8 * 8]) =
            *reinterpret_cast<const uint4*>(&Qgl[(size_t)(i0 + row) * DH + c8 * 8]);
    }
    __syncthreads();

    uint32_t qh[4][4], ql[4][4];
    #pragma unroll
    for (int ks = 0; ks < 4; ks++) {
        int row = 16 * wrp + (mm & 1) * 8 + mr;
        int col = ks * 16 + (mm >> 1) * 8;
        ldsm4(qh[ks][0], qh[ks][1], qh[ks][2], qh[ks][3], &Qh[row][col]);
        ldsm4(ql[ks][0], ql[ks][1], ql[ks][2], ql[ks][3], &Ql[row][col]);
    }

    float m0_ = -1e30f, m1_ = -1e30f, l0_ = 0.f, l1_ = 0.f;
    float o[8][4];
    #pragma unroll
    for (int f = 0; f < 8; f++)
        #pragma unroll
        for (int e = 0; e < 4; e++) o[f][e] = 0.f;

    for (int jt = 0; jt < 16; jt++) {
        int j0 = jt * 64;
        __syncthreads();   // Q frags read / previous PV reads complete before overwrite
        #pragma unroll
        for (int e = 0; e < 2; e++) {
            int lin = e * 256 + t;
            int row = lin >> 3, c8 = lin & 7;
            size_t g = (size_t)(j0 + row) * DH + c8 * 8;
            *reinterpret_cast<uint4*>(&Kh[row][c8 * 8]) = *reinterpret_cast<const uint4*>(&Kgh[g]);
            *reinterpret_cast<uint4*>(&Kl[row][c8 * 8]) = *reinterpret_cast<const uint4*>(&Kgl[g]);
            *reinterpret_cast<uint4*>(&Vh[row][c8 * 8]) = *reinterpret_cast<const uint4*>(&Vgh[g]);
            *reinterpret_cast<uint4*>(&Vl[row][c8 * 8]) = *reinterpret_cast<const uint4*>(&Vgl[g]);
        }
        if (t < 64) maskS[t] = g_mask[(j0 + t) * BB + b];
        __syncthreads();

        // S = Q K^T (Q pre-scaled)
        float s[8][4];
        #pragma unroll
        for (int f = 0; f < 8; f++)
            #pragma unroll
            for (int e = 0; e < 4; e++) s[f][e] = 0.f;
        #pragma unroll
        for (int ks = 0; ks < 4; ks++) {
            uint32_t kbh[8][2], kbl[8][2];
            #pragma unroll
            for (int p = 0; p < 4; p++) {
                int jrow = (p * 2 + (mm >> 1)) * 8 + mr;
                int dcol = ks * 16 + (mm & 1) * 8;
                uint32_t r0, r1, r2, r3;
                ldsm4(r0, r1, r2, r3, &Kh[jrow][dcol]);
                kbh[2*p][0] = r0; kbh[2*p][1] = r1; kbh[2*p+1][0] = r2; kbh[2*p+1][1] = r3;
                ldsm4(r0, r1, r2, r3, &Kl[jrow][dcol]);
                kbl[2*p][0] = r0; kbl[2*p][1] = r1; kbl[2*p+1][0] = r2; kbl[2*p+1][1] = r3;
            }
            #pragma unroll
            for (int f = 0; f < 8; f++) {
                mma_bf16(s[f][0], s[f][1], s[f][2], s[f][3],
                         qh[ks][0], qh[ks][1], qh[ks][2], qh[ks][3], kbh[f][0], kbh[f][1]);
                mma_bf16(s[f][0], s[f][1], s[f][2], s[f][3],
                         qh[ks][0], qh[ks][1], qh[ks][2], qh[ks][3], kbl[f][0], kbl[f][1]);
                mma_bf16(s[f][0], s[f][1], s[f][2], s[f][3],
                         ql[ks][0], ql[ks][1], ql[ks][2], ql[ks][3], kbh[f][0], kbh[f][1]);
            }
        }
        // mask (exact replace with -10000)
        #pragma unroll
        for (int f = 0; f < 8; f++) {
            if (maskS[8 * f + 2 * tig])     { s[f][0] = -1e4f; s[f][2] = -1e4f; }
            if (maskS[8 * f + 2 * tig + 1]) { s[f][1] = -1e4f; s[f][3] = -1e4f; }
        }
        // online softmax: row0 = gid, row1 = gid+8 (quad = 4 lanes share a row)
        float mx0 = -1e30f, mx1 = -1e30f;
        #pragma unroll
        for (int f = 0; f < 8; f++) {
            mx0 = fmaxf(mx0, fmaxf(s[f][0], s[f][1]));
            mx1 = fmaxf(mx1, fmaxf(s[f][2], s[f][3]));
        }
        mx0 = fmaxf(mx0, __shfl_xor_sync(0xffffffffu, mx0, 1));
        mx0 = fmaxf(mx0, __shfl_xor_sync(0xffffffffu, mx0, 2));
        mx1 = fmaxf(mx1, __shfl_xor_sync(0xffffffffu, mx1, 1));
        mx1 = fmaxf(mx1, __shfl_xor_sync(0xffffffffu, mx1, 2));
        float mn0 = fmaxf(m0_, mx0), mn1 = fmaxf(m1_, mx1);
        float sc0 = __expf(m0_ - mn0), sc1 = __expf(m1_ - mn1);
        m0_ = mn0; m1_ = mn1;
        float sum0 = 0.f, sum1 = 0.f;
        #pragma unroll
        for (int f = 0; f < 8; f++) {
            s[f][0] = __expf(s[f][0] - mn0);
            s[f][1] = __expf(s[f][1] - mn0);
            s[f][2] = __expf(s[f][2] - mn1);
            s[f][3] = __expf(s[f][3] - mn1);
            sum0 += s[f][0] + s[f][1];
            sum1 += s[f][2] + s[f][3];
        }
        sum0 += __shfl_xor_sync(0xffffffffu, sum0, 1);
        sum0 += __shfl_xor_sync(0xffffffffu, sum0, 2);
        sum1 += __shfl_xor_sync(0xffffffffu, sum1, 1);
        sum1 += __shfl_xor_sync(0xffffffffu, sum1, 2);
        l0_ = l0_ * sc0 + sum0;
        l1_ = l1_ * sc1 + sum1;
        #pragma unroll
        for (int f = 0; f < 8; f++) {
            o[f][0] *= sc0; o[f][1] *= sc0;
            o[f][2] *= sc1; o[f][3] *= sc1;
        }
        // O += P V  (P fragments repacked directly from S accumulators)
        #pragma unroll
        for (int kg = 0; kg < 4; kg++) {
            uint32_t ph[4], pl[4];
            {
                float p00 = s[2*kg][0],   p01 = s[2*kg][1],   p02 = s[2*kg][2],   p03 = s[2*kg][3];
                float p10 = s[2*kg+1][0], p11 = s[2*kg+1][1], p12 = s[2*kg+1][2], p13 = s[2*kg+1][3];
                split2(p00, p01, ph[0], pl[0]);
                split2(p02, p03, ph[1], pl[1]);
                split2(p10, p11, ph[2], pl[2]);
                split2(p12, p13, ph[3], pl[3]);
            }
            uint32_t vbh[8][2], vbl[8][2];
            #pragma unroll
            for (int p = 0; p < 4; p++) {
                int jrow = kg * 16 + (mm & 1) * 8 + mr;
                int dcol = (p * 2 + (mm >> 1)) * 8;
                uint32_t r0, r1, r2, r3;
                ldsm4t(r0, r1, r2, r3, &Vh[jrow][dcol]);
                vbh[2*p][0] = r0; vbh[2*p][1] = r1; vbh[2*p+1][0] = r2; vbh[2*p+1][1] = r3;
                ldsm4t(r0, r1, r2, r3, &Vl[jrow][dcol]);
                vbl[2*p][0] = r0; vbl[2*p][1] = r1; vbl[2*p+1][0] = r2; vbl[2*p+1][1] = r3;
            }
            #pragma unroll
            for (int f = 0; f < 8; f++) {
                mma_bf16(o[f][0], o[f][1], o[f][2], o[f][3],
                         ph[0], ph[1], ph[2], ph[3], vbh[f][0], vbh[f][1]);
                mma_bf16(o[f][0], o[f][1], o[f][2], o[f][3],
                         ph[0], ph[1], ph[2], ph[3], vbl[f][0], vbl[f][1]);
                mma_bf16(o[f][0], o[f][1], o[f][2], o[f][3],
                         pl[0], pl[1], pl[2], pl[3], vbh[f][0], vbh[f][1]);
            }
        }
    }

    // epilogue: divide by l, write fp32 g_attn
    float inv0 = 1.0f / l0_, inv1 = 1.0f / l1_;
    int i_loc = 16 * wrp + gid;
    #pragma unroll
    for (int f = 0; f < 8; f++) {
        int col = n * DH + 8 * f + 2 * tig;
        size_t row0 = ((size_t)(i0 + i_loc) * BB + b);
        size_t row1 = ((size_t)(i0 + i_loc + 8) * BB + b);
        float2 w0 = make_float2(o[f][0] * inv0, o[f][1] * inv0);
        float2 w1 = make_float2(o[f][2] * inv1, o[f][3] * inv1);
        *reinterpret_cast<float2*>(&g_attn[row0 * NDH + col]) = w0;
        *reinterpret_cast<float2*>(&g_attn[row1 * NDH + col]) = w1;
    }
}

// ---------------- launch ----------------
extern "C" void kernel_launch(void* const* d_in, const int* in_sizes, int n_in,
                              void* d_out, int out_size) {
    const float* h     = (const float*)d_in[0];
    const float* c     = (const float*)d_in[1];
    const void*  mask  = d_in[2];
    const float* Wq    = (const float*)d_in[3];
    const float* Wkv   = (const float*)d_in[4];
    const float* Wo    = (const float*)d_in[5];
    const float* gamma = (const float*)d_in[6];
    const float* beta  = (const float*)d_in[7];
    float* out = (float*)d_out;

    mask_kernel<<<1, 256>>>((const unsigned int*)mask, (const unsigned char*)mask);
    ln_kernel<<<ROWS, 256>>>(h, gamma, beta);
    sgemm_mma<1><<<dim3(16, 64), 256>>>(c, Wkv, nullptr, DM, 2 * NDH);   // K,V proj
    sgemm_mma<0><<<dim3(8, 64), 256>>>(nullptr, Wq, nullptr, DM, NDH);   // Q proj
    attn_kernel<<<dim3(8, 128), 256>>>();
    sgemm_mma<2><<<dim3(8, 64), 256>>>(nullptr, Wo, out, NDH, DM);       // O proj + residual
}

// round 4
// speedup vs baseline: 2.4764x; 1.1924x over previous
#include <cuda_runtime.h>
#include <cuda_bf16.h>
#include <math.h>
#include <stdint.h>

#define QL   1024
#define KVL  1024
#define BB   8
#define DM   1024
#define NH   16
#define DH   64
#define ROWS (QL*BB)     // 8192
#define NDH  (NH*DH)     // 1024

// ---------------- scratch (device globals) ----------------
__device__ __align__(16) float g_hln[ROWS*DM];              // LN(h) fp32 residual
__device__ __align__(16) __nv_bfloat16 g_hln_h[ROWS*DM];
__device__ __align__(16) __nv_bfloat16 g_hln_l[ROWS*DM];
__device__ __align__(16) __nv_bfloat16 g_c_h[ROWS*DM];
__device__ __align__(16) __nv_bfloat16 g_c_l[ROWS*DM];
__device__ __align__(16) __nv_bfloat16 g_wq_h[DM*NDH];
__device__ __align__(16) __nv_bfloat16 g_wq_l[DM*NDH];
__device__ __align__(16) __nv_bfloat16 g_wkv_h[DM*2*NDH];
__device__ __align__(16) __nv_bfloat16 g_wkv_l[DM*2*NDH];
__device__ __align__(16) __nv_bfloat16 g_wo_h[NDH*DM];
__device__ __align__(16) __nv_bfloat16 g_wo_l[NDH*DM];
__device__ __align__(16) __nv_bfloat16 g_q_h[BB*NH*QL*DH];
__device__ __align__(16) __nv_bfloat16 g_q_l[BB*NH*QL*DH];
__device__ __align__(16) __nv_bfloat16 g_k_h[BB*NH*KVL*DH];
__device__ __align__(16) __nv_bfloat16 g_k_l[BB*NH*KVL*DH];
__device__ __align__(16) __nv_bfloat16 g_v_h[BB*NH*KVL*DH];
__device__ __align__(16) __nv_bfloat16 g_v_l[BB*NH*KVL*DH];
__device__ __align__(16) __nv_bfloat16 g_attn_h[ROWS*NDH];
__device__ __align__(16) __nv_bfloat16 g_attn_l[ROWS*NDH];
__device__ int g_mask[KVL*BB];

// ---------------- helpers ----------------
__device__ __forceinline__ void ldsm4(uint32_t &r0, uint32_t &r1, uint32_t &r2, uint32_t &r3,
                                      const void* p) {
    uint32_t a = (uint32_t)__cvta_generic_to_shared(p);
    asm volatile("ldmatrix.sync.aligned.m8n8.x4.shared.b16 {%0,%1,%2,%3},[%4];\n"
                 : "=r"(r0), "=r"(r1), "=r"(r2), "=r"(r3) : "r"(a));
}
__device__ __forceinline__ void ldsm4t(uint32_t &r0, uint32_t &r1, uint32_t &r2, uint32_t &r3,
                                       const void* p) {
    uint32_t a = (uint32_t)__cvta_generic_to_shared(p);
    asm volatile("ldmatrix.sync.aligned.m8n8.x4.trans.shared.b16 {%0,%1,%2,%3},[%4];\n"
                 : "=r"(r0), "=r"(r1), "=r"(r2), "=r"(r3) : "r"(a));
}
__device__ __forceinline__ void mma_bf16(float &c0, float &c1, float &c2, float &c3,
                                         uint32_t a0, uint32_t a1, uint32_t a2, uint32_t a3,
                                         uint32_t b0, uint32_t b1) {
    asm volatile(
        "mma.sync.aligned.m16n8k16.row.col.f32.bf16.bf16.f32 "
        "{%0,%1,%2,%3},{%4,%5,%6,%7},{%8,%9},{%0,%1,%2,%3};\n"
        : "+f"(c0), "+f"(c1), "+f"(c2), "+f"(c3)
        : "r"(a0), "r"(a1), "r"(a2), "r"(a3), "r"(b0), "r"(b1));
}
__device__ __forceinline__ uint32_t packbf(__nv_bfloat16 x, __nv_bfloat16 y) {
    return ((uint32_t)__bfloat16_as_ushort(y) << 16) | (uint32_t)__bfloat16_as_ushort(x);
}
__device__ __forceinline__ void split2(float x, float y, uint32_t &hi, uint32_t &lo) {
    __nv_bfloat16 hx = __float2bfloat16_rn(x), hy = __float2bfloat16_rn(y);
    __nv_bfloat16 lx = __float2bfloat16_rn(x - __bfloat162float(hx));
    __nv_bfloat16 ly = __float2bfloat16_rn(y - __bfloat162float(hy));
    hi = packbf(hx, hy);
    lo = packbf(lx, ly);
}
__device__ __forceinline__ void cpasync16(void* smem, const void* g) {
    uint32_t a = (uint32_t)__cvta_generic_to_shared(smem);
    asm volatile("cp.async.cg.shared.global [%0],[%1],16;\n" :: "r"(a), "l"(g));
}
__device__ __forceinline__ void cp_commit() { asm volatile("cp.async.commit_group;\n"); }
template<int N> __device__ __forceinline__ void cp_wait() {
    asm volatile("cp.async.wait_group %0;\n" :: "n"(N));
}

// ---------------- mask detect + canonicalize ----------------
__global__ void mask_kernel(const unsigned int* __restrict__ mw,
                            const unsigned char* __restrict__ mb) {
    __shared__ int s_w01, s_f01;
    int t = threadIdx.x;
    if (t == 0) { s_w01 = 1; s_f01 = 1; }
    __syncthreads();
    int w01 = 1, f01 = 1;
    for (int i = t; i < 2048; i += 256) {
        unsigned int w = mw[i];
        if (w > 1u) w01 = 0;
        if (w != 0u && w != 0x3F800000u) f01 = 0;
    }
    if (!w01) atomicAnd(&s_w01, 0);
    if (!f01) atomicAnd(&s_f01, 0);
    __syncthreads();
    bool word_mode = (s_w01 != 0) || (s_f01 != 0);
    for (int e = t; e < KVL*BB; e += 256) {
        int v = word_mode ? (mw[e] != 0u) : (mb[e] != 0);
        g_mask[e] = v;
    }
}

// ---------------- fp32 -> bf16 hi/lo split (elementwise) ----------------
__global__ void conv_split(const float4* __restrict__ src,
                           uint2* __restrict__ dh, uint2* __restrict__ dl, int n4) {
    int i = blockIdx.x * blockDim.x + threadIdx.x;
    if (i < n4) {
        float4 v = src[i];
        uint32_t h0, l0, h1, l1;
        split2(v.x, v.y, h0, l0);
        split2(v.z, v.w, h1, l1);
        dh[i] = make_uint2(h0, h1);
        dl[i] = make_uint2(l0, l1);
    }
}

// ---------------- layernorm: writes fp32 residual + bf16 hi/lo ----------------
__global__ void ln_kernel(const float* __restrict__ h,
                          const float* __restrict__ gamma,
                          const float* __restrict__ beta) {
    int row = blockIdx.x;
    int t = threadIdx.x;
    const float4* hp = reinterpret_cast<const float4*>(h + (size_t)row * DM);
    float4 x = hp[t];
    float s  = x.x + x.y + x.z + x.w;
    float ss = x.x*x.x + x.y*x.y + x.z*x.z + x.w*x.w;
    #pragma unroll
    for (int off = 16; off; off >>= 1) {
        s  += __shfl_xor_sync(0xffffffffu, s,  off);
        ss += __shfl_xor_sync(0xffffffffu, ss, off);
    }
    __shared__ float sh_s[8], sh_ss[8];
    __shared__ float s_mu, s_rstd;
    if ((t & 31) == 0) { sh_s[t >> 5] = s; sh_ss[t >> 5] = ss; }
    __syncthreads();
    if (t == 0) {
        float S = 0.f, SS = 0.f;
        #pragma unroll
        for (int i = 0; i < 8; i++) { S += sh_s[i]; SS += sh_ss[i]; }
        float mu  = S / DM;
        float var = SS / DM - mu * mu;
        s_mu = mu;
        s_rstd = rsqrtf(var + 1e-5f);
    }
    __syncthreads();
    float mu = s_mu, r = s_rstd;
    const float4* gp = reinterpret_cast<const float4*>(gamma);
    const float4* bp = reinterpret_cast<const float4*>(beta);
    float4 g = gp[t], bt = bp[t];
    float4 o;
    o.x = (x.x - mu) * r * g.x + bt.x;
    o.y = (x.y - mu) * r * g.y + bt.y;
    o.z = (x.z - mu) * r * g.z + bt.z;
    o.w = (x.w - mu) * r * g.w + bt.w;
    size_t base = (size_t)row * DM + t * 4;
    *reinterpret_cast<float4*>(&g_hln[base]) = o;
    uint32_t h0, l0, h1, l1;
    split2(o.x, o.y, h0, l0);
    split2(o.z, o.w, h1, l1);
    *reinterpret_cast<uint2*>(&g_hln_h[base]) = make_uint2(h0, h1);
    *reinterpret_cast<uint2*>(&g_hln_l[base]) = make_uint2(l0, l1);
}

// ---------------- bf16-split tensor GEMM, cp.async double-buffered ----------------
// C[128x128] per CTA, K in 32-chunks. MODE 0: ->q (scaled); 1: ->k/v; 2: out=res+C
#define AS_STRIDE 40
#define BS_STRIDE 136
#define STG_ELEMS (128*AS_STRIDE*2 + 32*BS_STRIDE*2)   // 18944 bf16 per stage
#define OFF_AH 0
#define OFF_AL (128*AS_STRIDE)
#define OFF_BH (2*128*AS_STRIDE)
#define OFF_BL (2*128*AS_STRIDE + 32*BS_STRIDE)

template<int MODE>
__global__ __launch_bounds__(256, 2)
void gemm_bf16(const __nv_bfloat16* __restrict__ Ah_g, const __nv_bfloat16* __restrict__ Al_g,
               const __nv_bfloat16* __restrict__ Bh_g, const __nv_bfloat16* __restrict__ Bl_g,
               float* __restrict__ out, int K, int N) {
    extern __shared__ __nv_bfloat16 sm[];

    int t = threadIdx.x;
    int lane = t & 31, wrp = t >> 5;
    int gid = lane >> 2, tig = lane & 3;
    int wm = wrp & 3, wn = wrp >> 2;
    int m0 = blockIdx.y * 128, n0 = blockIdx.x * 128;
    int mm = lane >> 3, mr = lane & 7;

    // cp.async chunk coordinates (per thread: 2 A-chunks, 2 B-chunks per hi/lo)
    int idA0 = t,        idA1 = t + 256;          // A: row=id>>2, c4=id&3 (8 bf16 chunks)
    int rA0 = idA0 >> 2, cA0 = idA0 & 3;
    int rA1 = idA1 >> 2, cA1 = idA1 & 3;
    int rB0 = idA0 >> 4, cB0 = idA0 & 15;         // B: row=id>>4, c=id&15
    int rB1 = idA1 >> 4, cB1 = idA1 & 15;

    auto issue = [&](int kt, int st) {
        __nv_bfloat16* S = sm + st * STG_ELEMS;
        size_t ga0 = (size_t)(m0 + rA0) * K + kt + cA0 * 8;
        size_t ga1 = (size_t)(m0 + rA1) * K + kt + cA1 * 8;
        cpasync16(&S[OFF_AH + rA0 * AS_STRIDE + cA0 * 8], &Ah_g[ga0]);
        cpasync16(&S[OFF_AH + rA1 * AS_STRIDE + cA1 * 8], &Ah_g[ga1]);
        cpasync16(&S[OFF_AL + rA0 * AS_STRIDE + cA0 * 8], &Al_g[ga0]);
        cpasync16(&S[OFF_AL + rA1 * AS_STRIDE + cA1 * 8], &Al_g[ga1]);
        size_t gb0 = (size_t)(kt + rB0) * N + n0 + cB0 * 8;
        size_t gb1 = (size_t)(kt + rB1) * N + n0 + cB1 * 8;
        cpasync16(&S[OFF_BH + rB0 * BS_STRIDE + cB0 * 8], &Bh_g[gb0]);
        cpasync16(&S[OFF_BH + rB1 * BS_STRIDE + cB1 * 8], &Bh_g[gb1]);
        cpasync16(&S[OFF_BL + rB0 * BS_STRIDE + cB0 * 8], &Bl_g[gb0]);
        cpasync16(&S[OFF_BL + rB1 * BS_STRIDE + cB1 * 8], &Bl_g[gb1]);
        cp_commit();
    };

    float acc[2][8][4];
    #pragma unroll
    for (int i = 0; i < 2; i++)
        #pragma unroll
        for (int f = 0; f < 8; f++)
            #pragma unroll
            for (int e = 0; e < 4; e++) acc[i][f][e] = 0.f;

    int NT = K >> 5;
    issue(0, 0);
    for (int it = 0; it < NT; it++) {
        int cur = it & 1;
        if (it + 1 < NT) { issue((it + 1) << 5, cur ^ 1); cp_wait<1>(); }
        else             { cp_wait<0>(); }
        __syncthreads();

        __nv_bfloat16 (*Ah)[AS_STRIDE] =
            reinterpret_cast<__nv_bfloat16(*)[AS_STRIDE]>(sm + cur * STG_ELEMS + OFF_AH);
        __nv_bfloat16 (*Al)[AS_STRIDE] =
            reinterpret_cast<__nv_bfloat16(*)[AS_STRIDE]>(sm + cur * STG_ELEMS + OFF_AL);
        __nv_bfloat16 (*Bh)[BS_STRIDE] =
            reinterpret_cast<__nv_bfloat16(*)[BS_STRIDE]>(sm + cur * STG_ELEMS + OFF_BH);
        __nv_bfloat16 (*Bl)[BS_STRIDE] =
            reinterpret_cast<__nv_bfloat16(*)[BS_STRIDE]>(sm + cur * STG_ELEMS + OFF_BL);

        #pragma unroll
        for (int kk = 0; kk < 32; kk += 16) {
            uint32_t ah[2][4], al[2][4];
            #pragma unroll
            for (int im = 0; im < 2; im++) {
                int row = 32 * wm + 16 * im + (mm & 1) * 8 + mr;
                int col = kk + (mm >> 1) * 8;
                ldsm4(ah[im][0], ah[im][1], ah[im][2], ah[im][3], &Ah[row][col]);
                ldsm4(al[im][0], al[im][1], al[im][2], al[im][3], &Al[row][col]);
            }
            uint32_t bh[8][2], bl[8][2];
            #pragma unroll
            for (int p = 0; p < 4; p++) {
                int krow = kk + (mm & 1) * 8 + mr;
                int ncol = 64 * wn + p * 16 + (mm >> 1) * 8;
                uint32_t r0, r1, r2, r3;
                ldsm4t(r0, r1, r2, r3, &Bh[krow][ncol]);
                bh[2*p][0] = r0; bh[2*p][1] = r1; bh[2*p+1][0] = r2; bh[2*p+1][1] = r3;
                ldsm4t(r0, r1, r2, r3, &Bl[krow][ncol]);
                bl[2*p][0] = r0; bl[2*p][1] = r1; bl[2*p+1][0] = r2; bl[2*p+1][1] = r3;
            }
            #pragma unroll
            for (int im = 0; im < 2; im++)
                #pragma unroll
                for (int f = 0; f < 8; f++) {
                    mma_bf16(acc[im][f][0], acc[im][f][1], acc[im][f][2], acc[im][f][3],
                             ah[im][0], ah[im][1], ah[im][2], ah[im][3], bh[f][0], bh[f][1]);
                    mma_bf16(acc[im][f][0], acc[im][f][1], acc[im][f][2], acc[im][f][3],
                             ah[im][0], ah[im][1], ah[im][2], ah[im][3], bl[f][0], bl[f][1]);
                    mma_bf16(acc[im][f][0], acc[im][f][1], acc[im][f][2], acc[im][f][3],
                             al[im][0], al[im][1], al[im][2], al[im][3], bh[f][0], bh[f][1]);
                }
        }
        __syncthreads();
    }

    // epilogue
    #pragma unroll
    for (int im = 0; im < 2; im++) {
        #pragma unroll
        for (int f = 0; f < 8; f++) {
            int cb = n0 + 64 * wn + 8 * f + 2 * tig;
            #pragma unroll
            for (int half = 0; half < 2; half++) {
                int r = m0 + 32 * wm + 16 * im + gid + half * 8;
                float v0 = acc[im][f][half * 2 + 0];
                float v1 = acc[im][f][half * 2 + 1];
                if (MODE == 0) {
                    v0 *= 0.125f; v1 *= 0.125f;
                    int ii = r >> 3, b = r & 7, n = cb >> 6, dh = cb & 63;
                    size_t base = (((size_t)(b * NH + n)) * QL + ii) * DH + dh;
                    uint32_t hp, lp;
                    split2(v0, v1, hp, lp);
                    *reinterpret_cast<uint32_t*>(&g_q_h[base]) = hp;
                    *reinterpret_cast<uint32_t*>(&g_q_l[base]) = lp;
                } else if (MODE == 1) {
                    int jj = r >> 3, b = r & 7;
                    uint32_t hp, lp;
                    split2(v0, v1, hp, lp);
                    if (cb < NDH) {
                        int n = cb >> 6, dh = cb & 63;
                        size_t base = (((size_t)(b * NH + n)) * KVL + jj) * DH + dh;
                        *reinterpret_cast<uint32_t*>(&g_k_h[base]) = hp;
                        *reinterpret_cast<uint32_t*>(&g_k_l[base]) = lp;
                    } else {
                        int c2 = cb - NDH;
                        int n = c2 >> 6, dh = c2 & 63;
                        size_t base = (((size_t)(b * NH + n)) * KVL + jj) * DH + dh;
                        *reinterpret_cast<uint32_t*>(&g_v_h[base]) = hp;
                        *reinterpret_cast<uint32_t*>(&g_v_l[base]) = lp;
                    }
                } else {
                    size_t o = (size_t)r * DM + cb;
                    out[o]     = g_hln[o]     + v0;
                    out[o + 1] = g_hln[o + 1] + v1;
                }
            }
        }
    }
}

// ---------------- flash attention (unchanged core; bf16 hi/lo epilogue) ----------------
#define ATS 72
__global__ __launch_bounds__(256)
void attn_kernel() {
    __shared__ __align__(16) __nv_bfloat16 smt[256 * ATS];
    __shared__ int maskS[64];
    __nv_bfloat16 (*Qh)[ATS] = reinterpret_cast<__nv_bfloat16(*)[ATS]>(smt);
    __nv_bfloat16 (*Ql)[ATS] = reinterpret_cast<__nv_bfloat16(*)[ATS]>(smt + 128 * ATS);
    __nv_bfloat16 (*Kh)[ATS] = reinterpret_cast<__nv_bfloat16(*)[ATS]>(smt);
    __nv_bfloat16 (*Kl)[ATS] = reinterpret_cast<__nv_bfloat16(*)[ATS]>(smt + 64 * ATS);
    __nv_bfloat16 (*Vh)[ATS] = reinterpret_cast<__nv_bfloat16(*)[ATS]>(smt + 128 * ATS);
    __nv_bfloat16 (*Vl)[ATS] = reinterpret_cast<__nv_bfloat16(*)[ATS]>(smt + 192 * ATS);

    int t = threadIdx.x;
    int lane = t & 31, wrp = t >> 5;
    int gid = lane >> 2, tig = lane & 3;
    int mm = lane >> 3, mr = lane & 7;
    int i0 = blockIdx.x * 128;
    int bn = blockIdx.y;
    int b = bn >> 4, n = bn & 15;

    const __nv_bfloat16* Qgh = g_q_h + (size_t)bn * QL * DH;
    const __nv_bfloat16* Qgl = g_q_l + (size_t)bn * QL * DH;
    const __nv_bfloat16* Kgh = g_k_h + (size_t)bn * KVL * DH;
    const __nv_bfloat16* Kgl = g_k_l + (size_t)bn * KVL * DH;
    const __nv_bfloat16* Vgh = g_v_h + (size_t)bn * KVL * DH;
    const __nv_bfloat16* Vgl = g_v_l + (size_t)bn * KVL * DH;

    #pragma unroll
    for (int e = 0; e < 4; e++) {
        int lin = e * 256 + t;
        int row = lin >> 3, c8 = lin & 7;
        *reinterpret_cast<uint4*>(&Qh[row][c8 * 8]) =
            *reinterpret_cast<const uint4*>(&Qgh[(size_t)(i0 + row) * DH + c8 * 8]);
        *reinterpret_cast<uint4*>(&Ql[row][c8 * 8]) =
            *reinterpret_cast<const uint4*>(&Qgl[(size_t)(i0 + row) * DH + c8 * 8]);
    }
    __syncthreads();

    uint32_t qh[4][4], ql[4][4];
    #pragma unroll
    for (int ks = 0; ks < 4; ks++) {
        int row = 16 * wrp + (mm & 1) * 8 + mr;
        int col = ks * 16 + (mm >> 1) * 8;
        ldsm4(qh[ks][0], qh[ks][1], qh[ks][2], qh[ks][3], &Qh[row][col]);
        ldsm4(ql[ks][0], ql[ks][1], ql[ks][2], ql[ks][3], &Ql[row][col]);
    }

    float m0_ = -1e30f, m1_ = -1e30f, l0_ = 0.f, l1_ = 0.f;
    float o[8][4];
    #pragma unroll
    for (int f = 0; f < 8; f++)
        #pragma unroll
        for (int e = 0; e < 4; e++) o[f][e] = 0.f;

    for (int jt = 0; jt < 16; jt++) {
        int j0 = jt * 64;
        __syncthreads();
        #pragma unroll
        for (int e = 0; e < 2; e++) {
            int lin = e * 256 + t;
            int row = lin >> 3, c8 = lin & 7;
            size_t g = (size_t)(j0 + row) * DH + c8 * 8;
            *reinterpret_cast<uint4*>(&Kh[row][c8 * 8]) = *reinterpret_cast<const uint4*>(&Kgh[g]);
            *reinterpret_cast<uint4*>(&Kl[row][c8 * 8]) = *reinterpret_cast<const uint4*>(&Kgl[g]);
            *reinterpret_cast<uint4*>(&Vh[row][c8 * 8]) = *reinterpret_cast<const uint4*>(&Vgh[g]);
            *reinterpret_cast<uint4*>(&Vl[row][c8 * 8]) = *reinterpret_cast<const uint4*>(&Vgl[g]);
        }
        if (t < 64) maskS[t] = g_mask[(j0 + t) * BB + b];
        __syncthreads();

        float s[8][4];
        #pragma unroll
        for (int f = 0; f < 8; f++)
            #pragma unroll
            for (int e = 0; e < 4; e++) s[f][e] = 0.f;
        #pragma unroll
        for (int ks = 0; ks < 4; ks++) {
            uint32_t kbh[8][2], kbl[8][2];
            #pragma unroll
            for (int p = 0; p < 4; p++) {
                int jrow = (p * 2 + (mm >> 1)) * 8 + mr;
                int dcol = ks * 16 + (mm & 1) * 8;
                uint32_t r0, r1, r2, r3;
                ldsm4(r0, r1, r2, r3, &Kh[jrow][dcol]);
                kbh[2*p][0] = r0; kbh[2*p][1] = r1; kbh[2*p+1][0] = r2; kbh[2*p+1][1] = r3;
                ldsm4(r0, r1, r2, r3, &Kl[jrow][dcol]);
                kbl[2*p][0] = r0; kbl[2*p][1] = r1; kbl[2*p+1][0] = r2; kbl[2*p+1][1] = r3;
            }
            #pragma unroll
            for (int f = 0; f < 8; f++) {
                mma_bf16(s[f][0], s[f][1], s[f][2], s[f][3],
                         qh[ks][0], qh[ks][1], qh[ks][2], qh[ks][3], kbh[f][0], kbh[f][1]);
                mma_bf16(s[f][0], s[f][1], s[f][2], s[f][3],
                         qh[ks][0], qh[ks][1], qh[ks][2], qh[ks][3], kbl[f][0], kbl[f][1]);
                mma_bf16(s[f][0], s[f][1], s[f][2], s[f][3],
                         ql[ks][0], ql[ks][1], ql[ks][2], ql[ks][3], kbh[f][0], kbh[f][1]);
            }
        }
        #pragma unroll
        for (int f = 0; f < 8; f++) {
            if (maskS[8 * f + 2 * tig])     { s[f][0] = -1e4f; s[f][2] = -1e4f; }
            if (maskS[8 * f + 2 * tig + 1]) { s[f][1] = -1e4f; s[f][3] = -1e4f; }
        }
        float mx0 = -1e30f, mx1 = -1e30f;
        #pragma unroll
        for (int f = 0; f < 8; f++) {
            mx0 = fmaxf(mx0, fmaxf(s[f][0], s[f][1]));
            mx1 = fmaxf(mx1, fmaxf(s[f][2], s[f][3]));
        }
        mx0 = fmaxf(mx0, __shfl_xor_sync(0xffffffffu, mx0, 1));
        mx0 = fmaxf(mx0, __shfl_xor_sync(0xffffffffu, mx0, 2));
        mx1 = fmaxf(mx1, __shfl_xor_sync(0xffffffffu, mx1, 1));
        mx1 = fmaxf(mx1, __shfl_xor_sync(0xffffffffu, mx1, 2));
        float mn0 = fmaxf(m0_, mx0), mn1 = fmaxf(m1_, mx1);
        float sc0 = __expf(m0_ - mn0), sc1 = __expf(m1_ - mn1);
        m0_ = mn0; m1_ = mn1;
        float sum0 = 0.f, sum1 = 0.f;
        #pragma unroll
        for (int f = 0; f < 8; f++) {
            s[f][0] = __expf(s[f][0] - mn0);
            s[f][1] = __expf(s[f][1] - mn0);
            s[f][2] = __expf(s[f][2] - mn1);
            s[f][3] = __expf(s[f][3] - mn1);
            sum0 += s[f][0] + s[f][1];
            sum1 += s[f][2] + s[f][3];
        }
        sum0 += __shfl_xor_sync(0xffffffffu, sum0, 1);
        sum0 += __shfl_xor_sync(0xffffffffu, sum0, 2);
        sum1 += __shfl_xor_sync(0xffffffffu, sum1, 1);
        sum1 += __shfl_xor_sync(0xffffffffu, sum1, 2);
        l0_ = l0_ * sc0 + sum0;
        l1_ = l1_ * sc1 + sum1;
        #pragma unroll
        for (int f = 0; f < 8; f++) {
            o[f][0] *= sc0; o[f][1] *= sc0;
            o[f][2] *= sc1; o[f][3] *= sc1;
        }
        #pragma unroll
        for (int kg = 0; kg < 4; kg++) {
            uint32_t ph[4], pl[4];
            {
                split2(s[2*kg][0],   s[2*kg][1],   ph[0], pl[0]);
                split2(s[2*kg][2],   s[2*kg][3],   ph[1], pl[1]);
                split2(s[2*kg+1][0], s[2*kg+1][1], ph[2], pl[2]);
                split2(s[2*kg+1][2], s[2*kg+1][3], ph[3], pl[3]);
            }
            uint32_t vbh[8][2], vbl[8][2];
            #pragma unroll
            for (int p = 0; p < 4; p++) {
                int jrow = kg * 16 + (mm & 1) * 8 + mr;
                int dcol = (p * 2 + (mm >> 1)) * 8;
                uint32_t r0, r1, r2, r3;
                ldsm4t(r0, r1, r2, r3, &Vh[jrow][dcol]);
                vbh[2*p][0] = r0; vbh[2*p][1] = r1; vbh[2*p+1][0] = r2; vbh[2*p+1][1] = r3;
                ldsm4t(r0, r1, r2, r3, &Vl[jrow][dcol]);
                vbl[2*p][0] = r0; vbl[2*p][1] = r1; vbl[2*p+1][0] = r2; vbl[2*p+1][1] = r3;
            }
            #pragma unroll
            for (int f = 0; f < 8; f++) {
                mma_bf16(o[f][0], o[f][1], o[f][2], o[f][3],
                         ph[0], ph[1], ph[2], ph[3], vbh[f][0], vbh[f][1]);
                mma_bf16(o[f][0], o[f][1], o[f][2], o[f][3],
                         ph[0], ph[1], ph[2], ph[3], vbl[f][0], vbl[f][1]);
                mma_bf16(o[f][0], o[f][1], o[f][2], o[f][3],
                         pl[0], pl[1], pl[2], pl[3], vbh[f][0], vbh[f][1]);
            }
        }
    }

    float inv0 = 1.0f / l0_, inv1 = 1.0f / l1_;
    int i_loc = 16 * wrp + gid;
    #pragma unroll
    for (int f = 0; f < 8; f++) {
        int col = n * DH + 8 * f + 2 * tig;
        size_t row0 = ((size_t)(i0 + i_loc) * BB + b);
        size_t row1 = ((size_t)(i0 + i_loc + 8) * BB + b);
        uint32_t hp, lp;
        split2(o[f][0] * inv0, o[f][1] * inv0, hp, lp);
        *reinterpret_cast<uint32_t*>(&g_attn_h[row0 * NDH + col]) = hp;
        *reinterpret_cast<uint32_t*>(&g_attn_l[row0 * NDH + col]) = lp;
        split2(o[f][2] * inv1, o[f][3] * inv1, hp, lp);
        *reinterpret_cast<uint32_t*>(&g_attn_h[row1 * NDH + col]) = hp;
        *reinterpret_cast<uint32_t*>(&g_attn_l[row1 * NDH + col]) = lp;
    }
}

// ---------------- launch ----------------
extern "C" void kernel_launch(void* const* d_in, const int* in_sizes, int n_in,
                              void* d_out, int out_size) {
    const float* h     = (const float*)d_in[0];
    const float* c     = (const float*)d_in[1];
    const void*  mask  = d_in[2];
    const float* Wq    = (const float*)d_in[3];
    const float* Wkv   = (const float*)d_in[4];
    const float* Wo    = (const float*)d_in[5];
    const float* gamma = (const float*)d_in[6];
    const float* beta  = (const float*)d_in[7];
    float* out = (float*)d_out;

    const int smem = 2 * STG_ELEMS * 2;   // 75776 bytes
    (void)cudaFuncSetAttribute(gemm_bf16<0>, cudaFuncAttributeMaxDynamicSharedMemorySize, smem);
    (void)cudaFuncSetAttribute(gemm_bf16<1>, cudaFuncAttributeMaxDynamicSharedMemorySize, smem);
    (void)cudaFuncSetAttribute(gemm_bf16<2>, cudaFuncAttributeMaxDynamicSharedMemorySize, smem);

    mask_kernel<<<1, 256>>>((const unsigned int*)mask, (const unsigned char*)mask);
    ln_kernel<<<ROWS, 256>>>(h, gamma, beta);

    __nv_bfloat16 *ch, *cl, *wqh, *wql, *wkvh, *wkvl, *woh, *wol;
    __nv_bfloat16 *hlh, *hll, *ath, *atl;
    cudaGetSymbolAddress((void**)&ch,  g_c_h);   cudaGetSymbolAddress((void**)&cl,  g_c_l);
    cudaGetSymbolAddress((void**)&wqh, g_wq_h);  cudaGetSymbolAddress((void**)&wql, g_wq_l);
    cudaGetSymbolAddress((void**)&wkvh,g_wkv_h); cudaGetSymbolAddress((void**)&wkvl,g_wkv_l);
    cudaGetSymbolAddress((void**)&woh, g_wo_h);  cudaGetSymbolAddress((void**)&wol, g_wo_l);
    cudaGetSymbolAddress((void**)&hlh, g_hln_h); cudaGetSymbolAddress((void**)&hll, g_hln_l);
    cudaGetSymbolAddress((void**)&ath, g_attn_h);cudaGetSymbolAddress((void**)&atl, g_attn_l);

    conv_split<<<(ROWS*DM/4 + 255)/256, 256>>>((const float4*)c,  (uint2*)ch,  (uint2*)cl,  ROWS*DM/4);
    conv_split<<<(DM*NDH/4 + 255)/256, 256>>>((const float4*)Wq,  (uint2*)wqh, (uint2*)wql, DM*NDH/4);
    conv_split<<<(DM*2*NDH/4 + 255)/256, 256>>>((const float4*)Wkv,(uint2*)wkvh,(uint2*)wkvl,DM*2*NDH/4);
    conv_split<<<(NDH*DM/4 + 255)/256, 256>>>((const float4*)Wo,  (uint2*)woh, (uint2*)wol, NDH*DM/4);

    gemm_bf16<1><<<dim3(16, 64), 256, smem>>>(ch,  cl,  wkvh, wkvl, nullptr, DM, 2 * NDH);
    gemm_bf16<0><<<dim3(8, 64), 256, smem>>>(hlh, hll, wqh,  wql,  nullptr, DM, NDH);
    attn_kernel<<<dim3(8, 128), 256>>>();
    gemm_bf16<2><<<dim3(8, 64), 256, smem>>>(ath, atl, woh,  wol,  out,     NDH, DM);
}

// round 9
// speedup vs baseline: 2.4853x; 1.0036x over previous
#include <cuda_runtime.h>
#include <cuda_bf16.h>
#include <math.h>
#include <stdint.h>

#define QL   1024
#define KVL  1024
#define BB   8
#define DM   1024
#define NH   16
#define DH   64
#define ROWS (QL*BB)     // 8192
#define NDH  (NH*DH)     // 1024

// ---------------- scratch (device globals) ----------------
__device__ __align__(16) float g_hln[ROWS*DM];              // LN(h) fp32 residual
__device__ __align__(16) __nv_bfloat16 g_hln_h[ROWS*DM];
__device__ __align__(16) __nv_bfloat16 g_hln_l[ROWS*DM];
__device__ __align__(16) __nv_bfloat16 g_c_h[ROWS*DM];
__device__ __align__(16) __nv_bfloat16 g_c_l[ROWS*DM];
__device__ __align__(16) __nv_bfloat16 g_wq_h[DM*NDH];
__device__ __align__(16) __nv_bfloat16 g_wq_l[DM*NDH];
__device__ __align__(16) __nv_bfloat16 g_wkv_h[DM*2*NDH];
__device__ __align__(16) __nv_bfloat16 g_wkv_l[DM*2*NDH];
__device__ __align__(16) __nv_bfloat16 g_wo_h[NDH*DM];
__device__ __align__(16) __nv_bfloat16 g_wo_l[NDH*DM];
__device__ __align__(16) __nv_bfloat16 g_q_h[BB*NH*QL*DH];
__device__ __align__(16) __nv_bfloat16 g_q_l[BB*NH*QL*DH];
__device__ __align__(16) __nv_bfloat16 g_k_h[BB*NH*KVL*DH];
__device__ __align__(16) __nv_bfloat16 g_k_l[BB*NH*KVL*DH];
__device__ __align__(16) __nv_bfloat16 g_v_h[BB*NH*KVL*DH];
__device__ __align__(16) __nv_bfloat16 g_v_l[BB*NH*KVL*DH];
__device__ __align__(16) __nv_bfloat16 g_attn_h[ROWS*NDH];
__device__ __align__(16) __nv_bfloat16 g_attn_l[ROWS*NDH];
__device__ __align__(16) int g_maskT[BB*KVL];               // [b][j], 1 = masked

// ---------------- helpers ----------------
__device__ __forceinline__ void ldsm4(uint32_t &r0, uint32_t &r1, uint32_t &r2, uint32_t &r3,
                                      const void* p) {
    uint32_t a = (uint32_t)__cvta_generic_to_shared(p);
    asm volatile("ldmatrix.sync.aligned.m8n8.x4.shared.b16 {%0,%1,%2,%3},[%4];\n"
                 : "=r"(r0), "=r"(r1), "=r"(r2), "=r"(r3) : "r"(a));
}
__device__ __forceinline__ void ldsm4t(uint32_t &r0, uint32_t &r1, uint32_t &r2, uint32_t &r3,
                                       const void* p) {
    uint32_t a = (uint32_t)__cvta_generic_to_shared(p);
    asm volatile("ldmatrix.sync.aligned.m8n8.x4.trans.shared.b16 {%0,%1,%2,%3},[%4];\n"
                 : "=r"(r0), "=r"(r1), "=r"(r2), "=r"(r3) : "r"(a));
}
__device__ __forceinline__ void mma_bf16(float &c0, float &c1, float &c2, float &c3,
                                         uint32_t a0, uint32_t a1, uint32_t a2, uint32_t a3,
                                         uint32_t b0, uint32_t b1) {
    asm volatile(
        "mma.sync.aligned.m16n8k16.row.col.f32.bf16.bf16.f32 "
        "{%0,%1,%2,%3},{%4,%5,%6,%7},{%8,%9},{%0,%1,%2,%3};\n"
        : "+f"(c0), "+f"(c1), "+f"(c2), "+f"(c3)
        : "r"(a0), "r"(a1), "r"(a2), "r"(a3), "r"(b0), "r"(b1));
}
__device__ __forceinline__ uint32_t packbf(__nv_bfloat16 x, __nv_bfloat16 y) {
    return ((uint32_t)__bfloat16_as_ushort(y) << 16) | (uint32_t)__bfloat16_as_ushort(x);
}
__device__ __forceinline__ void split2(float x, float y, uint32_t &hi, uint32_t &lo) {
    __nv_bfloat16 hx = __float2bfloat16_rn(x), hy = __float2bfloat16_rn(y);
    __nv_bfloat16 lx = __float2bfloat16_rn(x - __bfloat162float(hx));
    __nv_bfloat16 ly = __float2bfloat16_rn(y - __bfloat162float(hy));
    hi = packbf(hx, hy);
    lo = packbf(lx, ly);
}
__device__ __forceinline__ void cpasync16s(uint32_t s, const void* g) {
    asm volatile("cp.async.cg.shared.global [%0],[%1],16;\n" :: "r"(s), "l"(g));
}
__device__ __forceinline__ void cp_commit() { asm volatile("cp.async.commit_group;\n"); }
template<int N> __device__ __forceinline__ void cp_wait() {
    asm volatile("cp.async.wait_group %0;\n" :: "n"(N));
}

// ---------------- mask detect + canonicalize (writes transposed [b][j]) ----------------
__global__ void mask_kernel(const unsigned int* __restrict__ mw,
                            const unsigned char* __restrict__ mb) {
    __shared__ int s_w01, s_f01;
    int t = threadIdx.x;
    if (t == 0) { s_w01 = 1; s_f01 = 1; }
    __syncthreads();
    int w01 = 1, f01 = 1;
    for (int i = t; i < 2048; i += 256) {
        unsigned int w = mw[i];
        if (w > 1u) w01 = 0;
        if (w != 0u && w != 0x3F800000u) f01 = 0;
    }
    if (!w01) atomicAnd(&s_w01, 0);
    if (!f01) atomicAnd(&s_f01, 0);
    __syncthreads();
    bool word_mode = (s_w01 != 0) || (s_f01 != 0);
    for (int e = t; e < KVL*BB; e += 256) {
        int j = e >> 3, b = e & 7;
        int v = word_mode ? (mw[e] != 0u) : (mb[e] != 0);
        g_maskT[b * KVL + j] = v;
    }
}

// ---------------- fp32 -> bf16 hi/lo split (elementwise) ----------------
__global__ void conv_split(const float4* __restrict__ src,
                           uint2* __restrict__ dh, uint2* __restrict__ dl, int n4) {
    int i = blockIdx.x * blockDim.x + threadIdx.x;
    if (i < n4) {
        float4 v = src[i];
        uint32_t h0, l0, h1, l1;
        split2(v.x, v.y, h0, l0);
        split2(v.z, v.w, h1, l1);
        dh[i] = make_uint2(h0, h1);
        dl[i] = make_uint2(l0, l1);
    }
}

// ---------------- layernorm: fp32 residual + bf16 hi/lo ----------------
__global__ void ln_kernel(const float* __restrict__ h,
                          const float* __restrict__ gamma,
                          const float* __restrict__ beta) {
    int row = blockIdx.x;
    int t = threadIdx.x;
    const float4* hp = reinterpret_cast<const float4*>(h + (size_t)row * DM);
    float4 x = hp[t];
    float s  = x.x + x.y + x.z + x.w;
    float ss = x.x*x.x + x.y*x.y + x.z*x.z + x.w*x.w;
    #pragma unroll
    for (int off = 16; off; off >>= 1) {
        s  += __shfl_xor_sync(0xffffffffu, s,  off);
        ss += __shfl_xor_sync(0xffffffffu, ss, off);
    }
    __shared__ float sh_s[8], sh_ss[8];
    __shared__ float s_mu, s_rstd;
    if ((t & 31) == 0) { sh_s[t >> 5] = s; sh_ss[t >> 5] = ss; }
    __syncthreads();
    if (t == 0) {
        float S = 0.f, SS = 0.f;
        #pragma unroll
        for (int i = 0; i < 8; i++) { S += sh_s[i]; SS += sh_ss[i]; }
        float mu  = S / DM;
        float var = SS / DM - mu * mu;
        s_mu = mu;
        s_rstd = rsqrtf(var + 1e-5f);
    }
    __syncthreads();
    float mu = s_mu, r = s_rstd;
    const float4* gp = reinterpret_cast<const float4*>(gamma);
    const float4* bp = reinterpret_cast<const float4*>(beta);
    float4 g = gp[t], bt = bp[t];
    float4 o;
    o.x = (x.x - mu) * r * g.x + bt.x;
    o.y = (x.y - mu) * r * g.y + bt.y;
    o.z = (x.z - mu) * r * g.z + bt.z;
    o.w = (x.w - mu) * r * g.w + bt.w;
    size_t base = (size_t)row * DM + t * 4;
    *reinterpret_cast<float4*>(&g_hln[base]) = o;
    uint32_t h0, l0, h1, l1;
    split2(o.x, o.y, h0, l0);
    split2(o.z, o.w, h1, l1);
    *reinterpret_cast<uint2*>(&g_hln_h[base]) = make_uint2(h0, h1);
    *reinterpret_cast<uint2*>(&g_hln_l[base]) = make_uint2(l0, l1);
}

// ---------------- bf16-split tensor GEMM, cp.async 3-stage pipeline ----------------
#define AS_STRIDE 40
#define BS_STRIDE 136
#define STG_ELEMS (128*AS_STRIDE*2 + 32*BS_STRIDE*2)   // 18944 bf16 per stage
#define OFF_AH 0
#define OFF_AL (128*AS_STRIDE)
#define OFF_BH (2*128*AS_STRIDE)
#define OFF_BL (2*128*AS_STRIDE + 32*BS_STRIDE)

template<int MODE>
__global__ __launch_bounds__(256, 2)
void gemm_bf16(const __nv_bfloat16* __restrict__ Ah_g, const __nv_bfloat16* __restrict__ Al_g,
               const __nv_bfloat16* __restrict__ Bh_g, const __nv_bfloat16* __restrict__ Bl_g,
               float* __restrict__ out, int K, int N) {
    extern __shared__ __nv_bfloat16 sm[];
    uint32_t smb = (uint32_t)__cvta_generic_to_shared(sm);

    int t = threadIdx.x;
    int lane = t & 31, wrp = t >> 5;
    int gid = lane >> 2, tig = lane & 3;
    int wm = wrp & 3, wn = wrp >> 2;
    int m0 = blockIdx.y * 128, n0 = blockIdx.x * 128;
    int mm = lane >> 3, mr = lane & 7;

    int rA0 = t >> 2,          cA0 = t & 3;
    int rA1 = (t + 256) >> 2,  cA1 = (t + 256) & 3;
    int rB0 = t >> 4,          cB0 = t & 15;
    int rB1 = (t + 256) >> 4,  cB1 = (t + 256) & 15;

    auto issue = [&](int kt, int st) {
        uint32_t S = smb + st * STG_ELEMS * 2;
        size_t ga0 = (size_t)(m0 + rA0) * K + kt + cA0 * 8;
        size_t ga1 = (size_t)(m0 + rA1) * K + kt + cA1 * 8;
        cpasync16s(S + (OFF_AH + rA0 * AS_STRIDE + cA0 * 8) * 2, &Ah_g[ga0]);
        cpasync16s(S + (OFF_AH + rA1 * AS_STRIDE + cA1 * 8) * 2, &Ah_g[ga1]);
        cpasync16s(S + (OFF_AL + rA0 * AS_STRIDE + cA0 * 8) * 2, &Al_g[ga0]);
        cpasync16s(S + (OFF_AL + rA1 * AS_STRIDE + cA1 * 8) * 2, &Al_g[ga1]);
        size_t gb0 = (size_t)(kt + rB0) * N + n0 + cB0 * 8;
        size_t gb1 = (size_t)(kt + rB1) * N + n0 + cB1 * 8;
        cpasync16s(S + (OFF_BH + rB0 * BS_STRIDE + cB0 * 8) * 2, &Bh_g[gb0]);
        cpasync16s(S + (OFF_BH + rB1 * BS_STRIDE + cB1 * 8) * 2, &Bh_g[gb1]);
        cpasync16s(S + (OFF_BL + rB0 * BS_STRIDE + cB0 * 8) * 2, &Bl_g[gb0]);
        cpasync16s(S + (OFF_BL + rB1 * BS_STRIDE + cB1 * 8) * 2, &Bl_g[gb1]);
        cp_commit();
    };

    float acc[2][8][4];
    #pragma unroll
    for (int i = 0; i < 2; i++)
        #pragma unroll
        for (int f = 0; f < 8; f++)
            #pragma unroll
            for (int e = 0; e < 4; e++) acc[i][f][e] = 0.f;

    int NT = K >> 5;
    issue(0, 0);
    issue(32, 1);
    for (int it = 0; it < NT; it++) {
        int cur = it % 3;
        if (it + 2 < NT) { issue((it + 2) << 5, (it + 2) % 3); cp_wait<2>(); }
        else if (it + 1 < NT) cp_wait<1>();
        else cp_wait<0>();
        __syncthreads();

        __nv_bfloat16 (*Ah)[AS_STRIDE] =
            reinterpret_cast<__nv_bfloat16(*)[AS_STRIDE]>(sm + cur * STG_ELEMS + OFF_AH);
        __nv_bfloat16 (*Al)[AS_STRIDE] =
            reinterpret_cast<__nv_bfloat16(*)[AS_STRIDE]>(sm + cur * STG_ELEMS + OFF_AL);
        __nv_bfloat16 (*Bh)[BS_STRIDE] =
            reinterpret_cast<__nv_bfloat16(*)[BS_STRIDE]>(sm + cur * STG_ELEMS + OFF_BH);
        __nv_bfloat16 (*Bl)[BS_STRIDE] =
            reinterpret_cast<__nv_bfloat16(*)[BS_STRIDE]>(sm + cur * STG_ELEMS + OFF_BL);

        #pragma unroll
        for (int kk = 0; kk < 32; kk += 16) {
            uint32_t ah[2][4], al[2][4];
            #pragma unroll
            for (int im = 0; im < 2; im++) {
                int row = 32 * wm + 16 * im + (mm & 1) * 8 + mr;
                int col = kk + (mm >> 1) * 8;
                ldsm4(ah[im][0], ah[im][1], ah[im][2], ah[im][3], &Ah[row][col]);
                ldsm4(al[im][0], al[im][1], al[im][2], al[im][3], &Al[row][col]);
            }
            uint32_t bh[8][2], bl[8][2];
            #pragma unroll
            for (int p = 0; p < 4; p++) {
                int krow = kk + (mm & 1) * 8 + mr;
                int ncol = 64 * wn + p * 16 + (mm >> 1) * 8;
                uint32_t r0, r1, r2, r3;
                ldsm4t(r0, r1, r2, r3, &Bh[krow][ncol]);
                bh[2*p][0] = r0; bh[2*p][1] = r1; bh[2*p+1][0] = r2; bh[2*p+1][1] = r3;
                ldsm4t(r0, r1, r2, r3, &Bl[krow][ncol]);
                bl[2*p][0] = r0; bl[2*p][1] = r1; bl[2*p+1][0] = r2; bl[2*p+1][1] = r3;
            }
            #pragma unroll
            for (int im = 0; im < 2; im++)
                #pragma unroll
                for (int f = 0; f < 8; f++) {
                    mma_bf16(acc[im][f][0], acc[im][f][1], acc[im][f][2], acc[im][f][3],
                             ah[im][0], ah[im][1], ah[im][2], ah[im][3], bh[f][0], bh[f][1]);
                    mma_bf16(acc[im][f][0], acc[im][f][1], acc[im][f][2], acc[im][f][3],
                             ah[im][0], ah[im][1], ah[im][2], ah[im][3], bl[f][0], bl[f][1]);
                    mma_bf16(acc[im][f][0], acc[im][f][1], acc[im][f][2], acc[im][f][3],
                             al[im][0], al[im][1], al[im][2], al[im][3], bh[f][0], bh[f][1]);
                }
        }
        __syncthreads();
    }

    // epilogue
    #pragma unroll
    for (int im = 0; im < 2; im++) {
        #pragma unroll
        for (int f = 0; f < 8; f++) {
            int cb = n0 + 64 * wn + 8 * f + 2 * tig;
            #pragma unroll
            for (int half = 0; half < 2; half++) {
                int r = m0 + 32 * wm + 16 * im + gid + half * 8;
                float v0 = acc[im][f][half * 2 + 0];
                float v1 = acc[im][f][half * 2 + 1];
                if (MODE == 0) {
                    v0 *= 0.125f; v1 *= 0.125f;
                    int ii = r >> 3, b = r & 7, n = cb >> 6, dh = cb & 63;
                    size_t base = (((size_t)(b * NH + n)) * QL + ii) * DH + dh;
                    uint32_t hp, lp; split2(v0, v1, hp, lp);
                    *reinterpret_cast<uint32_t*>(&g_q_h[base]) = hp;
                    *reinterpret_cast<uint32_t*>(&g_q_l[base]) = lp;
                } else if (MODE == 1) {
                    int jj = r >> 3, b = r & 7;
                    uint32_t hp, lp; split2(v0, v1, hp, lp);
                    if (cb < NDH) {
                        int n = cb >> 6, dh = cb & 63;
                        size_t base = (((size_t)(b * NH + n)) * KVL + jj) * DH + dh;
                        *reinterpret_cast<uint32_t*>(&g_k_h[base]) = hp;
                        *reinterpret_cast<uint32_t*>(&g_k_l[base]) = lp;
                    } else {
                        int c2 = cb - NDH, n = c2 >> 6, dh = c2 & 63;
                        size_t base = (((size_t)(b * NH + n)) * KVL + jj) * DH + dh;
                        *reinterpret_cast<uint32_t*>(&g_v_h[base]) = hp;
                        *reinterpret_cast<uint32_t*>(&g_v_l[base]) = lp;
                    }
                } else {
                    size_t o = (size_t)r * DM + cb;
                    out[o]     = g_hln[o]     + v0;
                    out[o + 1] = g_hln[o + 1] + v1;
                }
            }
        }
    }
}

// ---------------- flash attention: cp.async double-buffered K/V ----------------
// dyn smem: 2 stages x (Kh,Kl,Vh,Vl each [64][72]) = 73728 B; Q phase reuses region
#define ATS 72
#define STGA (4*64*ATS)   // elems per stage = 18432
__global__ __launch_bounds__(256)
void attn_kernel() {
    extern __shared__ __nv_bfloat16 dynA[];
    __shared__ __align__(16) int maskSS[2][64];
    uint32_t sbA = (uint32_t)__cvta_generic_to_shared(dynA);
    uint32_t sbM = (uint32_t)__cvta_generic_to_shared(&maskSS[0][0]);

    int t = threadIdx.x;
    int lane = t & 31, wrp = t >> 5;
    int gid = lane >> 2, tig = lane & 3;
    int mm = lane >> 3, mr = lane & 7;
    int i0 = blockIdx.x * 128;
    int bn = blockIdx.y;
    int b = bn >> 4, n = bn & 15;

    const __nv_bfloat16* Qgh = g_q_h + (size_t)bn * QL * DH;
    const __nv_bfloat16* Qgl = g_q_l + (size_t)bn * QL * DH;
    const __nv_bfloat16* Kgh = g_k_h + (size_t)bn * KVL * DH;
    const __nv_bfloat16* Kgl = g_k_l + (size_t)bn * KVL * DH;
    const __nv_bfloat16* Vgh = g_v_h + (size_t)bn * KVL * DH;
    const __nv_bfloat16* Vgl = g_v_l + (size_t)bn * KVL * DH;

    // ---- Q phase: load 128x64 hi/lo into start of dyn region, hoist frags ----
    {
        __nv_bfloat16 (*Qh)[ATS] = reinterpret_cast<__nv_bfloat16(*)[ATS]>(dynA);
        __nv_bfloat16 (*Ql)[ATS] = reinterpret_cast<__nv_bfloat16(*)[ATS]>(dynA + 128 * ATS);
        #pragma unroll
        for (int e = 0; e < 4; e++) {
            int lin = e * 256 + t;
            int row = lin >> 3, c8 = lin & 7;
            *reinterpret_cast<uint4*>(&Qh[row][c8 * 8]) =
                *reinterpret_cast<const uint4*>(&Qgh[(size_t)(i0 + row) * DH + c8 * 8]);
            *reinterpret_cast<uint4*>(&Ql[row][c8 * 8]) =
                *reinterpret_cast<const uint4*>(&Qgl[(size_t)(i0 + row) * DH + c8 * 8]);
        }
    }
    __syncthreads();
    uint32_t qh[4][4], ql[4][4];
    {
        __nv_bfloat16 (*Qh)[ATS] = reinterpret_cast<__nv_bfloat16(*)[ATS]>(dynA);
        __nv_bfloat16 (*Ql)[ATS] = reinterpret_cast<__nv_bfloat16(*)[ATS]>(dynA + 128 * ATS);
        #pragma unroll
        for (int ks = 0; ks < 4; ks++) {
            int row = 16 * wrp + (mm & 1) * 8 + mr;
            int col = ks * 16 + (mm >> 1) * 8;
            ldsm4(qh[ks][0], qh[ks][1], qh[ks][2], qh[ks][3], &Qh[row][col]);
            ldsm4(ql[ks][0], ql[ks][1], ql[ks][2], ql[ks][3], &Ql[row][col]);
        }
    }
    __syncthreads();   // Q region free for stage buffers

    int rKV = t >> 3, cKV = t & 7;
    int rKV1 = (t + 256) >> 3, cKV1 = (t + 256) & 7;
    auto prefetch = [&](int jt, int buf) {
        int j0 = jt * 64;
        uint32_t base = sbA + buf * STGA * 2;
        {
            size_t g = (size_t)(j0 + rKV) * DH + cKV * 8;
            uint32_t so = (rKV * ATS + cKV * 8) * 2;
            cpasync16s(base + so,                  Kgh + g);
            cpasync16s(base + 64*ATS*2 + so,       Kgl + g);
            cpasync16s(base + 2*64*ATS*2 + so,     Vgh + g);
            cpasync16s(base + 3*64*ATS*2 + so,     Vgl + g);
        }
        {
            size_t g = (size_t)(j0 + rKV1) * DH + cKV1 * 8;
            uint32_t so = (rKV1 * ATS + cKV1 * 8) * 2;
            cpasync16s(base + so,                  Kgh + g);
            cpasync16s(base + 64*ATS*2 + so,       Kgl + g);
            cpasync16s(base + 2*64*ATS*2 + so,     Vgh + g);
            cpasync16s(base + 3*64*ATS*2 + so,     Vgl + g);
        }
        if (t < 16)
            cpasync16s(sbM + buf * 256 + t * 16, &g_maskT[b * KVL + j0 + t * 4]);
        cp_commit();
    };

    float m0_ = -1e30f, m1_ = -1e30f, l0_ = 0.f, l1_ = 0.f;
    float o[8][4];
    #pragma unroll
    for (int f = 0; f < 8; f++)
        #pragma unroll
        for (int e = 0; e < 4; e++) o[f][e] = 0.f;

    prefetch(0, 0);
    prefetch(1, 1);
    for (int jt = 0; jt < 16; jt++) {
        int buf = jt & 1;
        if (jt < 15) cp_wait<1>(); else cp_wait<0>();
        __syncthreads();

        __nv_bfloat16 (*Kh)[ATS] = reinterpret_cast<__nv_bfloat16(*)[ATS]>(dynA + buf * STGA);
        __nv_bfloat16 (*Kl)[ATS] = reinterpret_cast<__nv_bfloat16(*)[ATS]>(dynA + buf * STGA + 64 * ATS);
        __nv_bfloat16 (*Vh)[ATS] = reinterpret_cast<__nv_bfloat16(*)[ATS]>(dynA + buf * STGA + 2 * 64 * ATS);
        __nv_bfloat16 (*Vl)[ATS] = reinterpret_cast<__nv_bfloat16(*)[ATS]>(dynA + buf * STGA + 3 * 64 * ATS);
        const int* maskB = maskSS[buf];

        float s[8][4];
        #pragma unroll
        for (int f = 0; f < 8; f++)
            #pragma unroll
            for (int e = 0; e < 4; e++) s[f][e] = 0.f;
        #pragma unroll
        for (int ks = 0; ks < 4; ks++) {
            uint32_t kbh[8][2], kbl[8][2];
            #pragma unroll
            for (int p = 0; p < 4; p++) {
                int jrow = (p * 2 + (mm >> 1)) * 8 + mr;
                int dcol = ks * 16 + (mm & 1) * 8;
                uint32_t r0, r1, r2, r3;
                ldsm4(r0, r1, r2, r3, &Kh[jrow][dcol]);
                kbh[2*p][0] = r0; kbh[2*p][1] = r1; kbh[2*p+1][0] = r2; kbh[2*p+1][1] = r3;
                ldsm4(r0, r1, r2, r3, &Kl[jrow][dcol]);
                kbl[2*p][0] = r0; kbl[2*p][1] = r1; kbl[2*p+1][0] = r2; kbl[2*p+1][1] = r3;
            }
            #pragma unroll
            for (int f = 0; f < 8; f++) {
                mma_bf16(s[f][0], s[f][1], s[f][2], s[f][3],
                         qh[ks][0], qh[ks][1], qh[ks][2], qh[ks][3], kbh[f][0], kbh[f][1]);
                mma_bf16(s[f][0], s[f][1], s[f][2], s[f][3],
                         qh[ks][0], qh[ks][1], qh[ks][2], qh[ks][3], kbl[f][0], kbl[f][1]);
                mma_bf16(s[f][0], s[f][1], s[f][2], s[f][3],
                         ql[ks][0], ql[ks][1], ql[ks][2], ql[ks][3], kbh[f][0], kbh[f][1]);
            }
        }
        #pragma unroll
        for (int f = 0; f < 8; f++) {
            if (maskB[8 * f + 2 * tig])     { s[f][0] = -1e4f; s[f][2] = -1e4f; }
            if (maskB[8 * f + 2 * tig + 1]) { s[f][1] = -1e4f; s[f][3] = -1e4f; }
        }
        float mx0 = -1e30f, mx1 = -1e30f;
        #pragma unroll
        for (int f = 0; f < 8; f++) {
            mx0 = fmaxf(mx0, fmaxf(s[f][0], s[f][1]));
            mx1 = fmaxf(mx1, fmaxf(s[f][2], s[f][3]));
        }
        mx0 = fmaxf(mx0, __shfl_xor_sync(0xffffffffu, mx0, 1));
        mx0 = fmaxf(mx0, __shfl_xor_sync(0xffffffffu, mx0, 2));
        mx1 = fmaxf(mx1, __shfl_xor_sync(0xffffffffu, mx1, 1));
        mx1 = fmaxf(mx1, __shfl_xor_sync(0xffffffffu, mx1, 2));
        float mn0 = fmaxf(m0_, mx0), mn1 = fmaxf(m1_, mx1);
        float sc0 = __expf(m0_ - mn0), sc1 = __expf(m1_ - mn1);
        m0_ = mn0; m1_ = mn1;
        float sum0 = 0.f, sum1 = 0.f;
        #pragma unroll
        for (int f = 0; f < 8; f++) {
            s[f][0] = __expf(s[f][0] - mn0);
            s[f][1] = __expf(s[f][1] - mn0);
            s[f][2] = __expf(s[f][2] - mn1);
            s[f][3] = __expf(s[f][3] - mn1);
            sum0 += s[f][0] + s[f][1];
            sum1 += s[f][2] + s[f][3];
        }
        sum0 += __shfl_xor_sync(0xffffffffu, sum0, 1);
        sum0 += __shfl_xor_sync(0xffffffffu, sum0, 2);
        sum1 += __shfl_xor_sync(0xffffffffu, sum1, 1);
        sum1 += __shfl_xor_sync(0xffffffffu, sum1, 2);
        l0_ = l0_ * sc0 + sum0;
        l1_ = l1_ * sc1 + sum1;
        #pragma unroll
        for (int f = 0; f < 8; f++) {
            o[f][0] *= sc0; o[f][1] *= sc0;
            o[f][2] *= sc1; o[f][3] *= sc1;
        }
        #pragma unroll
        for (int kg = 0; kg < 4; kg++) {
            uint32_t ph[4], pl[4];
            split2(s[2*kg][0],   s[2*kg][1],   ph[0], pl[0]);
            split2(s[2*kg][2],   s[2*kg][3],   ph[1], pl[1]);
            split2(s[2*kg+1][0], s[2*kg+1][1], ph[2], pl[2]);
            split2(s[2*kg+1][2], s[2*kg+1][3], ph[3], pl[3]);
            uint32_t vbh[8][2], vbl[8][2];
            #pragma unroll
            for (int p = 0; p < 4; p++) {
                int jrow = kg * 16 + (mm & 1) * 8 + mr;
                int dcol = (p * 2 + (mm >> 1)) * 8;
                uint32_t r0, r1, r2, r3;
                ldsm4t(r0, r1, r2, r3, &Vh[jrow][dcol]);
                vbh[2*p][0] = r0; vbh[2*p][1] = r1; vbh[2*p+1][0] = r2; vbh[2*p+1][1] = r3;
                ldsm4t(r0, r1, r2, r3, &Vl[jrow][dcol]);
                vbl[2*p][0] = r0; vbl[2*p][1] = r1; vbl[2*p+1][0] = r2; vbl[2*p+1][1] = r3;
            }
            #pragma unroll
            for (int f = 0; f < 8; f++) {
                mma_bf16(o[f][0], o[f][1], o[f][2], o[f][3],
                         ph[0], ph[1], ph[2], ph[3], vbh[f][0], vbh[f][1]);
                mma_bf16(o[f][0], o[f][1], o[f][2], o[f][3],
                         ph[0], ph[1], ph[2], ph[3], vbl[f][0], vbl[f][1]);
                mma_bf16(o[f][0], o[f][1], o[f][2], o[f][3],
                         pl[0], pl[1], pl[2], pl[3], vbh[f][0], vbh[f][1]);
            }
        }
        __syncthreads();   // all reads of this stage done
        if (jt + 2 < 16) prefetch(jt + 2, buf);
    }

    float inv0 = 1.0f / l0_, inv1 = 1.0f / l1_;
    int i_loc = 16 * wrp + gid;
    #pragma unroll
    for (int f = 0; f < 8; f++) {
        int col = n * DH + 8 * f + 2 * tig;
        size_t row0 = ((size_t)(i0 + i_loc) * BB + b);
        size_t row1 = ((size_t)(i0 + i_loc + 8) * BB + b);
        uint32_t hp, lp;
        split2(o[f][0] * inv0, o[f][1] * inv0, hp, lp);
        *reinterpret_cast<uint32_t*>(&g_attn_h[row0 * NDH + col]) = hp;
        *reinterpret_cast<uint32_t*>(&g_attn_l[row0 * NDH + col]) = lp;
        split2(o[f][2] * inv1, o[f][3] * inv1, hp, lp);
        *reinterpret_cast<uint32_t*>(&g_attn_h[row1 * NDH + col]) = hp;
        *reinterpret_cast<uint32_t*>(&g_attn_l[row1 * NDH + col]) = lp;
    }
}

// ---------------- launch ----------------
extern "C" void kernel_launch(void* const* d_in, const int* in_sizes, int n_in,
                              void* d_out, int out_size) {
    const float* h     = (const float*)d_in[0];
    const float* c     = (const float*)d_in[1];
    const void*  mask  = d_in[2];
    const float* Wq    = (const float*)d_in[3];
    const float* Wkv   = (const float*)d_in[4];
    const float* Wo    = (const float*)d_in[5];
    const float* gamma = (const float*)d_in[6];
    const float* beta  = (const float*)d_in[7];
    float* out = (float*)d_out;

    const int smemG = 3 * STG_ELEMS * 2;   // 113664 B
    const int smemA = 2 * STGA * 2;        // 73728 B
    (void)cudaFuncSetAttribute(gemm_bf16<0>, cudaFuncAttributeMaxDynamicSharedMemorySize, smemG);
    (void)cudaFuncSetAttribute(gemm_bf16<1>, cudaFuncAttributeMaxDynamicSharedMemorySize, smemG);
    (void)cudaFuncSetAttribute(gemm_bf16<2>, cudaFuncAttributeMaxDynamicSharedMemorySize, smemG);
    (void)cudaFuncSetAttribute(attn_kernel,  cudaFuncAttributeMaxDynamicSharedMemorySize, smemA);

    mask_kernel<<<1, 256>>>((const unsigned int*)mask, (const unsigned char*)mask);
    ln_kernel<<<ROWS, 256>>>(h, gamma, beta);

    __nv_bfloat16 *ch, *cl, *wqh, *wql, *wkvh, *wkvl, *woh, *wol;
    __nv_bfloat16 *hlh, *hll, *ath, *atl;
    cudaGetSymbolAddress((void**)&ch,  g_c_h);   cudaGetSymbolAddress((void**)&cl,  g_c_l);
    cudaGetSymbolAddress((void**)&wqh, g_wq_h);  cudaGetSymbolAddress((void**)&wql, g_wq_l);
    cudaGetSymbolAddress((void**)&wkvh,g_wkv_h); cudaGetSymbolAddress((void**)&wkvl,g_wkv_l);
    cudaGetSymbolAddress((void**)&woh, g_wo_h);  cudaGetSymbolAddress((void**)&wol, g_wo_l);
    cudaGetSymbolAddress((void**)&hlh, g_hln_h); cudaGetSymbolAddress((void**)&hll, g_hln_l);
    cudaGetSymbolAddress((void**)&ath, g_attn_h);cudaGetSymbolAddress((void**)&atl, g_attn_l);

    conv_split<<<(ROWS*DM/4 + 255)/256, 256>>>((const float4*)c,  (uint2*)ch,  (uint2*)cl,  ROWS*DM/4);
    conv_split<<<(DM*NDH/4 + 255)/256, 256>>>((const float4*)Wq,  (uint2*)wqh, (uint2*)wql, DM*NDH/4);
    conv_split<<<(DM*2*NDH/4 + 255)/256, 256>>>((const float4*)Wkv,(uint2*)wkvh,(uint2*)wkvl,DM*2*NDH/4);
    conv_split<<<(NDH*DM/4 + 255)/256, 256>>>((const float4*)Wo,  (uint2*)woh, (uint2*)wol, NDH*DM/4);

    gemm_bf16<1><<<dim3(16, 64), 256, smemG>>>(ch,  cl,  wkvh, wkvl, nullptr, DM, 2 * NDH);
    gemm_bf16<0><<<dim3(8, 64), 256, smemG>>>(hlh, hll, wqh,  wql,  nullptr, DM, NDH);
    attn_kernel<<<dim3(8, 128), 256, smemA>>>();
    gemm_bf16<2><<<dim3(8, 64), 256, smemG>>>(ath, atl, woh,  wol,  out,     NDH, DM);
}

// round 11
// speedup vs baseline: 2.6299x; 1.0582x over previous
#include <cuda_runtime.h>
#include <cuda_bf16.h>
#include <math.h>
#include <stdint.h>

#define QL   1024
#define KVL  1024
#define BB   8
#define DM   1024
#define NH   16
#define DH   64
#define ROWS (QL*BB)     // 8192
#define NDH  (NH*DH)     // 1024

// ---------------- scratch (device globals) ----------------
__device__ __align__(16) float g_hln[ROWS*DM];              // LN(h) fp32 residual
__device__ __align__(16) __nv_bfloat16 g_hln_h[ROWS*DM];
__device__ __align__(16) __nv_bfloat16 g_hln_l[ROWS*DM];
__device__ __align__(16) __nv_bfloat16 g_c_h[ROWS*DM];
__device__ __align__(16) __nv_bfloat16 g_c_l[ROWS*DM];
__device__ __align__(16) __nv_bfloat16 g_wq_h[DM*NDH];
__device__ __align__(16) __nv_bfloat16 g_wq_l[DM*NDH];
__device__ __align__(16) __nv_bfloat16 g_wkv_h[DM*2*NDH];
__device__ __align__(16) __nv_bfloat16 g_wkv_l[DM*2*NDH];
__device__ __align__(16) __nv_bfloat16 g_wo_h[NDH*DM];
__device__ __align__(16) __nv_bfloat16 g_wo_l[NDH*DM];
__device__ __align__(16) __nv_bfloat16 g_q_h[BB*NH*QL*DH];
__device__ __align__(16) __nv_bfloat16 g_q_l[BB*NH*QL*DH];
__device__ __align__(16) __nv_bfloat16 g_k_h[BB*NH*KVL*DH];
__device__ __align__(16) __nv_bfloat16 g_k_l[BB*NH*KVL*DH];
__device__ __align__(16) __nv_bfloat16 g_v_h[BB*NH*KVL*DH];
__device__ __align__(16) __nv_bfloat16 g_v_l[BB*NH*KVL*DH];
__device__ __align__(16) __nv_bfloat16 g_attn_h[ROWS*NDH];
__device__ __align__(16) __nv_bfloat16 g_attn_l[ROWS*NDH];
__device__ __align__(16) int g_maskT[BB*KVL];               // [b][j], 1 = masked

// ---------------- helpers ----------------
__device__ __forceinline__ void ldsm4(uint32_t &r0, uint32_t &r1, uint32_t &r2, uint32_t &r3,
                                      const void* p) {
    uint32_t a = (uint32_t)__cvta_generic_to_shared(p);
    asm volatile("ldmatrix.sync.aligned.m8n8.x4.shared.b16 {%0,%1,%2,%3},[%4];\n"
                 : "=r"(r0), "=r"(r1), "=r"(r2), "=r"(r3) : "r"(a));
}
__device__ __forceinline__ void ldsm4t(uint32_t &r0, uint32_t &r1, uint32_t &r2, uint32_t &r3,
                                       const void* p) {
    uint32_t a = (uint32_t)__cvta_generic_to_shared(p);
    asm volatile("ldmatrix.sync.aligned.m8n8.x4.trans.shared.b16 {%0,%1,%2,%3},[%4];\n"
                 : "=r"(r0), "=r"(r1), "=r"(r2), "=r"(r3) : "r"(a));
}
__device__ __forceinline__ void mma_bf16(float &c0, float &c1, float &c2, float &c3,
                                         uint32_t a0, uint32_t a1, uint32_t a2, uint32_t a3,
                                         uint32_t b0, uint32_t b1) {
    asm volatile(
        "mma.sync.aligned.m16n8k16.row.col.f32.bf16.bf16.f32 "
        "{%0,%1,%2,%3},{%4,%5,%6,%7},{%8,%9},{%0,%1,%2,%3};\n"
        : "+f"(c0), "+f"(c1), "+f"(c2), "+f"(c3)
        : "r"(a0), "r"(a1), "r"(a2), "r"(a3), "r"(b0), "r"(b1));
}
__device__ __forceinline__ uint32_t packbf(__nv_bfloat16 x, __nv_bfloat16 y) {
    return ((uint32_t)__bfloat16_as_ushort(y) << 16) | (uint32_t)__bfloat16_as_ushort(x);
}
__device__ __forceinline__ void split2(float x, float y, uint32_t &hi, uint32_t &lo) {
    __nv_bfloat16 hx = __float2bfloat16_rn(x), hy = __float2bfloat16_rn(y);
    __nv_bfloat16 lx = __float2bfloat16_rn(x - __bfloat162float(hx));
    __nv_bfloat16 ly = __float2bfloat16_rn(y - __bfloat162float(hy));
    hi = packbf(hx, hy);
    lo = packbf(lx, ly);
}
__device__ __forceinline__ void cpasync16s(uint32_t s, const void* g) {
    asm volatile("cp.async.cg.shared.global [%0],[%1],16;\n" :: "r"(s), "l"(g));
}
__device__ __forceinline__ void cp_commit() { asm volatile("cp.async.commit_group;\n"); }
template<int N> __device__ __forceinline__ void cp_wait() {
    asm volatile("cp.async.wait_group %0;\n" :: "n"(N));
}

// ---------------- mask detect + canonicalize (writes transposed [b][j]) ----------------
__global__ void mask_kernel(const unsigned int* __restrict__ mw,
                            const unsigned char* __restrict__ mb) {
    __shared__ int s_w01, s_f01;
    int t = threadIdx.x;
    if (t == 0) { s_w01 = 1; s_f01 = 1; }
    __syncthreads();
    int w01 = 1, f01 = 1;
    for (int i = t; i < 2048; i += 256) {
        unsigned int w = mw[i];
        if (w > 1u) w01 = 0;
        if (w != 0u && w != 0x3F800000u) f01 = 0;
    }
    if (!w01) atomicAnd(&s_w01, 0);
    if (!f01) atomicAnd(&s_f01, 0);
    __syncthreads();
    bool word_mode = (s_w01 != 0) || (s_f01 != 0);
    for (int e = t; e < KVL*BB; e += 256) {
        int j = e >> 3, b = e & 7;
        int v = word_mode ? (mw[e] != 0u) : (mb[e] != 0);
        g_maskT[b * KVL + j] = v;
    }
}

// ---------------- merged fp32 -> bf16 hi/lo split over 4 tensors ----------------
#define N4_C   (ROWS*DM/4)        // 2097152
#define N4_WQ  (DM*NDH/4)         // 262144
#define N4_WKV (DM*2*NDH/4)       // 524288
#define N4_WO  (NDH*DM/4)         // 262144
#define N4_TOT (N4_C + N4_WQ + N4_WKV + N4_WO)

__global__ void conv_split4(const float4* __restrict__ c,  const float4* __restrict__ wq,
                            const float4* __restrict__ wkv,const float4* __restrict__ wo,
                            uint2* __restrict__ ch,  uint2* __restrict__ cl,
                            uint2* __restrict__ wqh, uint2* __restrict__ wql,
                            uint2* __restrict__ wkvh,uint2* __restrict__ wkvl,
                            uint2* __restrict__ woh, uint2* __restrict__ wol) {
    int i = blockIdx.x * blockDim.x + threadIdx.x;
    if (i >= N4_TOT) return;
    const float4* src; uint2 *dh, *dl; int off;
    if (i < N4_C)                      { src = c;   dh = ch;   dl = cl;   off = i; }
    else if (i < N4_C + N4_WQ)         { src = wq;  dh = wqh;  dl = wql;  off = i - N4_C; }
    else if (i < N4_C + N4_WQ + N4_WKV){ src = wkv; dh = wkvh; dl = wkvl; off = i - N4_C - N4_WQ; }
    else                               { src = wo;  dh = woh;  dl = wol;  off = i - N4_C - N4_WQ - N4_WKV; }
    float4 v = src[off];
    uint32_t h0, l0, h1, l1;
    split2(v.x, v.y, h0, l0);
    split2(v.z, v.w, h1, l1);
    dh[off] = make_uint2(h0, h1);
    dl[off] = make_uint2(l0, l1);
}

// ---------------- layernorm: fp32 residual + bf16 hi/lo ----------------
__global__ void ln_kernel(const float* __restrict__ h,
                          const float* __restrict__ gamma,
                          const float* __restrict__ beta) {
    int row = blockIdx.x;
    int t = threadIdx.x;
    const float4* hp = reinterpret_cast<const float4*>(h + (size_t)row * DM);
    float4 x = hp[t];
    float s  = x.x + x.y + x.z + x.w;
    float ss = x.x*x.x + x.y*x.y + x.z*x.z + x.w*x.w;
    #pragma unroll
    for (int off = 16; off; off >>= 1) {
        s  += __shfl_xor_sync(0xffffffffu, s,  off);
        ss += __shfl_xor_sync(0xffffffffu, ss, off);
    }
    __shared__ float sh_s[8], sh_ss[8];
    __shared__ float s_mu, s_rstd;
    if ((t & 31) == 0) { sh_s[t >> 5] = s; sh_ss[t >> 5] = ss; }
    __syncthreads();
    if (t == 0) {
        float S = 0.f, SS = 0.f;
        #pragma unroll
        for (int i = 0; i < 8; i++) { S += sh_s[i]; SS += sh_ss[i]; }
        float mu  = S / DM;
        float var = SS / DM - mu * mu;
        s_mu = mu;
        s_rstd = rsqrtf(var + 1e-5f);
    }
    __syncthreads();
    float mu = s_mu, r = s_rstd;
    const float4* gp = reinterpret_cast<const float4*>(gamma);
    const float4* bp = reinterpret_cast<const float4*>(beta);
    float4 g = gp[t], bt = bp[t];
    float4 o;
    o.x = (x.x - mu) * r * g.x + bt.x;
    o.y = (x.y - mu) * r * g.y + bt.y;
    o.z = (x.z - mu) * r * g.z + bt.z;
    o.w = (x.w - mu) * r * g.w + bt.w;
    size_t base = (size_t)row * DM + t * 4;
    *reinterpret_cast<float4*>(&g_hln[base]) = o;
    uint32_t h0, l0, h1, l1;
    split2(o.x, o.y, h0, l0);
    split2(o.z, o.w, h1, l1);
    *reinterpret_cast<uint2*>(&g_hln_h[base]) = make_uint2(h0, h1);
    *reinterpret_cast<uint2*>(&g_hln_l[base]) = make_uint2(l0, l1);
}

// ---------------- bf16-split tensor GEMM core, cp.async 3-stage pipeline ----------------
// MODE 0: hln @ Wq -> q (scaled); MODE 1: c @ Wkv -> k/v; MODE 2: attn @ Wo -> out+res
#define AS_STRIDE 40
#define BS_STRIDE 136
#define STG_ELEMS (128*AS_STRIDE*2 + 32*BS_STRIDE*2)   // 18944 bf16 per stage
#define OFF_AH 0
#define OFF_AL (128*AS_STRIDE)
#define OFF_BH (2*128*AS_STRIDE)
#define OFF_BL (2*128*AS_STRIDE + 32*BS_STRIDE)

template<int MODE>
__device__ __forceinline__ void gemm_core(
    const __nv_bfloat16* __restrict__ Ah_g, const __nv_bfloat16* __restrict__ Al_g,
    const __nv_bfloat16* __restrict__ Bh_g, const __nv_bfloat16* __restrict__ Bl_g,
    float* __restrict__ out, int K, int N, int m0, int n0, __nv_bfloat16* sm) {
    uint32_t smb = (uint32_t)__cvta_generic_to_shared(sm);

    int t = threadIdx.x;
    int lane = t & 31, wrp = t >> 5;
    int gid = lane >> 2, tig = lane & 3;
    int wm = wrp & 3, wn = wrp >> 2;
    int mm = lane >> 3, mr = lane & 7;

    int rA0 = t >> 2,          cA0 = t & 3;
    int rA1 = (t + 256) >> 2,  cA1 = (t + 256) & 3;
    int rB0 = t >> 4,          cB0 = t & 15;
    int rB1 = (t + 256) >> 4,  cB1 = (t + 256) & 15;

    auto issue = [&](int kt, int st) {
        uint32_t S = smb + st * STG_ELEMS * 2;
        size_t ga0 = (size_t)(m0 + rA0) * K + kt + cA0 * 8;
        size_t ga1 = (size_t)(m0 + rA1) * K + kt + cA1 * 8;
        cpasync16s(S + (OFF_AH + rA0 * AS_STRIDE + cA0 * 8) * 2, &Ah_g[ga0]);
        cpasync16s(S + (OFF_AH + rA1 * AS_STRIDE + cA1 * 8) * 2, &Ah_g[ga1]);
        cpasync16s(S + (OFF_AL + rA0 * AS_STRIDE + cA0 * 8) * 2, &Al_g[ga0]);
        cpasync16s(S + (OFF_AL + rA1 * AS_STRIDE + cA1 * 8) * 2, &Al_g[ga1]);
        size_t gb0 = (size_t)(kt + rB0) * N + n0 + cB0 * 8;
        size_t gb1 = (size_t)(kt + rB1) * N + n0 + cB1 * 8;
        cpasync16s(S + (OFF_BH + rB0 * BS_STRIDE + cB0 * 8) * 2, &Bh_g[gb0]);
        cpasync16s(S + (OFF_BH + rB1 * BS_STRIDE + cB1 * 8) * 2, &Bh_g[gb1]);
        cpasync16s(S + (OFF_BL + rB0 * BS_STRIDE + cB0 * 8) * 2, &Bl_g[gb0]);
        cpasync16s(S + (OFF_BL + rB1 * BS_STRIDE + cB1 * 8) * 2, &Bl_g[gb1]);
        cp_commit();
    };

    float acc[2][8][4];
    #pragma unroll
    for (int i = 0; i < 2; i++)
        #pragma unroll
        for (int f = 0; f < 8; f++)
            #pragma unroll
            for (int e = 0; e < 4; e++) acc[i][f][e] = 0.f;

    int NT = K >> 5;
    issue(0, 0);
    issue(32, 1);
    for (int it = 0; it < NT; it++) {
        int cur = it % 3;
        if (it + 2 < NT) { issue((it + 2) << 5, (it + 2) % 3); cp_wait<2>(); }
        else if (it + 1 < NT) cp_wait<1>();
        else cp_wait<0>();
        __syncthreads();

        __nv_bfloat16 (*Ah)[AS_STRIDE] =
            reinterpret_cast<__nv_bfloat16(*)[AS_STRIDE]>(sm + cur * STG_ELEMS + OFF_AH);
        __nv_bfloat16 (*Al)[AS_STRIDE] =
            reinterpret_cast<__nv_bfloat16(*)[AS_STRIDE]>(sm + cur * STG_ELEMS + OFF_AL);
        __nv_bfloat16 (*Bh)[BS_STRIDE] =
            reinterpret_cast<__nv_bfloat16(*)[BS_STRIDE]>(sm + cur * STG_ELEMS + OFF_BH);
        __nv_bfloat16 (*Bl)[BS_STRIDE] =
            reinterpret_cast<__nv_bfloat16(*)[BS_STRIDE]>(sm + cur * STG_ELEMS + OFF_BL);

        #pragma unroll
        for (int kk = 0; kk < 32; kk += 16) {
            uint32_t ah[2][4], al[2][4];
            #pragma unroll
            for (int im = 0; im < 2; im++) {
                int row = 32 * wm + 16 * im + (mm & 1) * 8 + mr;
                int col = kk + (mm >> 1) * 8;
                ldsm4(ah[im][0], ah[im][1], ah[im][2], ah[im][3], &Ah[row][col]);
                ldsm4(al[im][0], al[im][1], al[im][2], al[im][3], &Al[row][col]);
            }
            uint32_t bh[8][2], bl[8][2];
            #pragma unroll
            for (int p = 0; p < 4; p++) {
                int krow = kk + (mm & 1) * 8 + mr;
                int ncol = 64 * wn + p * 16 + (mm >> 1) * 8;
                uint32_t r0, r1, r2, r3;
                ldsm4t(r0, r1, r2, r3, &Bh[krow][ncol]);
                bh[2*p][0] = r0; bh[2*p][1] = r1; bh[2*p+1][0] = r2; bh[2*p+1][1] = r3;
                ldsm4t(r0, r1, r2, r3, &Bl[krow][ncol]);
                bl[2*p][0] = r0; bl[2*p][1] = r1; bl[2*p+1][0] = r2; bl[2*p+1][1] = r3;
            }
            #pragma unroll
            for (int im = 0; im < 2; im++)
                #pragma unroll
                for (int f = 0; f < 8; f++) {
                    mma_bf16(acc[im][f][0], acc[im][f][1], acc[im][f][2], acc[im][f][3],
                             ah[im][0], ah[im][1], ah[im][2], ah[im][3], bh[f][0], bh[f][1]);
                    mma_bf16(acc[im][f][0], acc[im][f][1], acc[im][f][2], acc[im][f][3],
                             ah[im][0], ah[im][1], ah[im][2], ah[im][3], bl[f][0], bl[f][1]);
                    mma_bf16(acc[im][f][0], acc[im][f][1], acc[im][f][2], acc[im][f][3],
                             al[im][0], al[im][1], al[im][2], al[im][3], bh[f][0], bh[f][1]);
                }
        }
        __syncthreads();
    }

    // epilogue
    #pragma unroll
    for (int im = 0; im < 2; im++) {
        #pragma unroll
        for (int f = 0; f < 8; f++) {
            int cb = n0 + 64 * wn + 8 * f + 2 * tig;
            #pragma unroll
            for (int half = 0; half < 2; half++) {
                int r = m0 + 32 * wm + 16 * im + gid + half * 8;
                float v0 = acc[im][f][half * 2 + 0];
                float v1 = acc[im][f][half * 2 + 1];
                if (MODE == 0) {
                    v0 *= 0.125f; v1 *= 0.125f;
                    int ii = r >> 3, b = r & 7, n = cb >> 6, dh = cb & 63;
                    size_t base = (((size_t)(b * NH + n)) * QL + ii) * DH + dh;
                    uint32_t hp, lp; split2(v0, v1, hp, lp);
                    *reinterpret_cast<uint32_t*>(&g_q_h[base]) = hp;
                    *reinterpret_cast<uint32_t*>(&g_q_l[base]) = lp;
                } else if (MODE == 1) {
                    int jj = r >> 3, b = r & 7;
                    uint32_t hp, lp; split2(v0, v1, hp, lp);
                    if (cb < NDH) {
                        int n = cb >> 6, dh = cb & 63;
                        size_t base = (((size_t)(b * NH + n)) * KVL + jj) * DH + dh;
                        *reinterpret_cast<uint32_t*>(&g_k_h[base]) = hp;
                        *reinterpret_cast<uint32_t*>(&g_k_l[base]) = lp;
                    } else {
                        int c2 = cb - NDH, n = c2 >> 6, dh = c2 & 63;
                        size_t base = (((size_t)(b * NH + n)) * KVL + jj) * DH + dh;
                        *reinterpret_cast<uint32_t*>(&g_v_h[base]) = hp;
                        *reinterpret_cast<uint32_t*>(&g_v_l[base]) = lp;
                    }
                } else {
                    size_t o = (size_t)r * DM + cb;
                    out[o]     = g_hln[o]     + v0;
                    out[o + 1] = g_hln[o + 1] + v1;
                }
            }
        }
    }
}

// merged KV + Q projection: blockIdx.x < 16 -> KV tile, else Q tile
__global__ __launch_bounds__(256, 2)
void gemm_proj(const __nv_bfloat16* __restrict__ ch,  const __nv_bfloat16* __restrict__ cl,
               const __nv_bfloat16* __restrict__ wkvh,const __nv_bfloat16* __restrict__ wkvl,
               const __nv_bfloat16* __restrict__ hlh, const __nv_bfloat16* __restrict__ hll,
               const __nv_bfloat16* __restrict__ wqh, const __nv_bfloat16* __restrict__ wql) {
    extern __shared__ __nv_bfloat16 sm[];
    int m0 = blockIdx.y * 128;
    if (blockIdx.x < 16) {
        gemm_core<1>(ch, cl, wkvh, wkvl, nullptr, DM, 2 * NDH, m0, blockIdx.x * 128, sm);
    } else {
        gemm_core<0>(hlh, hll, wqh, wql, nullptr, DM, NDH, m0, (blockIdx.x - 16) * 128, sm);
    }
}

// output projection + residual
__global__ __launch_bounds__(256, 2)
void gemm_out(const __nv_bfloat16* __restrict__ ath, const __nv_bfloat16* __restrict__ atl,
              const __nv_bfloat16* __restrict__ woh, const __nv_bfloat16* __restrict__ wol,
              float* __restrict__ out) {
    extern __shared__ __nv_bfloat16 sm[];
    gemm_core<2>(ath, atl, woh, wol, out, NDH, DM, blockIdx.y * 128, blockIdx.x * 128, sm);
}

// ---------------- flash attention: cp.async double-buffered K/V ----------------
#define ATS 72
#define STGA (4*64*ATS)   // elems per stage = 18432
__global__ __launch_bounds__(256)
void attn_kernel() {
    extern __shared__ __nv_bfloat16 dynA[];
    __shared__ __align__(16) int maskSS[2][64];
    uint32_t sbA = (uint32_t)__cvta_generic_to_shared(dynA);
    uint32_t sbM = (uint32_t)__cvta_generic_to_shared(&maskSS[0][0]);

    int t = threadIdx.x;
    int lane = t & 31, wrp = t >> 5;
    int gid = lane >> 2, tig = lane & 3;
    int mm = lane >> 3, mr = lane & 7;
    int i0 = blockIdx.x * 128;
    int bn = blockIdx.y;
    int b = bn >> 4, n = bn & 15;

    const __nv_bfloat16* Qgh = g_q_h + (size_t)bn * QL * DH;
    const __nv_bfloat16* Qgl = g_q_l + (size_t)bn * QL * DH;
    const __nv_bfloat16* Kgh = g_k_h + (size_t)bn * KVL * DH;
    const __nv_bfloat16* Kgl = g_k_l + (size_t)bn * KVL * DH;
    const __nv_bfloat16* Vgh = g_v_h + (size_t)bn * KVL * DH;
    const __nv_bfloat16* Vgl = g_v_l + (size_t)bn * KVL * DH;

    // ---- Q phase: load 128x64 hi/lo into start of dyn region, hoist frags ----
    {
        __nv_bfloat16 (*Qh)[ATS] = reinterpret_cast<__nv_bfloat16(*)[ATS]>(dynA);
        __nv_bfloat16 (*Ql)[ATS] = reinterpret_cast<__nv_bfloat16(*)[ATS]>(dynA + 128 * ATS);
        #pragma unroll
        for (int e = 0; e < 4; e++) {
            int lin = e * 256 + t;
            int row = lin >> 3, c8 = lin & 7;
            *reinterpret_cast<uint4*>(&Qh[row][c8 * 8]) =
                *reinterpret_cast<const uint4*>(&Qgh[(size_t)(i0 + row) * DH + c8 * 8]);
            *reinterpret_cast<uint4*>(&Ql[row][c8 * 8]) =
                *reinterpret_cast<const uint4*>(&Qgl[(size_t)(i0 + row) * DH + c8 * 8]);
        }
    }
    __syncthreads();
    uint32_t qh[4][4], ql[4][4];
    {
        __nv_bfloat16 (*Qh)[ATS] = reinterpret_cast<__nv_bfloat16(*)[ATS]>(dynA);
        __nv_bfloat16 (*Ql)[ATS] = reinterpret_cast<__nv_bfloat16(*)[ATS]>(dynA + 128 * ATS);
        #pragma unroll
        for (int ks = 0; ks < 4; ks++) {
            int row = 16 * wrp + (mm & 1) * 8 + mr;
            int col = ks * 16 + (mm >> 1) * 8;
            ldsm4(qh[ks][0], qh[ks][1], qh[ks][2], qh[ks][3], &Qh[row][col]);
            ldsm4(ql[ks][0], ql[ks][1], ql[ks][2], ql[ks][3], &Ql[row][col]);
        }
    }
    __syncthreads();   // Q region free for stage buffers

    int rKV = t >> 3, cKV = t & 7;
    int rKV1 = (t + 256) >> 3, cKV1 = (t + 256) & 7;
    auto prefetch = [&](int jt, int buf) {
        int j0 = jt * 64;
        uint32_t base = sbA + buf * STGA * 2;
        {
            size_t g = (size_t)(j0 + rKV) * DH + cKV * 8;
            uint32_t so = (rKV * ATS + cKV * 8) * 2;
            cpasync16s(base + so,                  Kgh + g);
            cpasync16s(base + 64*ATS*2 + so,       Kgl + g);
            cpasync16s(base + 2*64*ATS*2 + so,     Vgh + g);
            cpasync16s(base + 3*64*ATS*2 + so,     Vgl + g);
        }
        {
            size_t g = (size_t)(j0 + rKV1) * DH + cKV1 * 8;
            uint32_t so = (rKV1 * ATS + cKV1 * 8) * 2;
            cpasync16s(base + so,                  Kgh + g);
            cpasync16s(base + 64*ATS*2 + so,       Kgl + g);
            cpasync16s(base + 2*64*ATS*2 + so,     Vgh + g);
            cpasync16s(base + 3*64*ATS*2 + so,     Vgl + g);
        }
        if (t < 16)
            cpasync16s(sbM + buf * 256 + t * 16, &g_maskT[b * KVL + j0 + t * 4]);
        cp_commit();
    };

    float m0_ = -1e30f, m1_ = -1e30f, l0_ = 0.f, l1_ = 0.f;
    float o[8][4];
    #pragma unroll
    for (int f = 0; f < 8; f++)
        #pragma unroll
        for (int e = 0; e < 4; e++) o[f][e] = 0.f;

    prefetch(0, 0);
    prefetch(1, 1);
    for (int jt = 0; jt < 16; jt++) {
        int buf = jt & 1;
        if (jt < 15) cp_wait<1>(); else cp_wait<0>();
        __syncthreads();

        __nv_bfloat16 (*Kh)[ATS] = reinterpret_cast<__nv_bfloat16(*)[ATS]>(dynA + buf * STGA);
        __nv_bfloat16 (*Kl)[ATS] = reinterpret_cast<__nv_bfloat16(*)[ATS]>(dynA + buf * STGA + 64 * ATS);
        __nv_bfloat16 (*Vh)[ATS] = reinterpret_cast<__nv_bfloat16(*)[ATS]>(dynA + buf * STGA + 2 * 64 * ATS);
        __nv_bfloat16 (*Vl)[ATS] = reinterpret_cast<__nv_bfloat16(*)[ATS]>(dynA + buf * STGA + 3 * 64 * ATS);
        const int* maskB = maskSS[buf];

        float s[8][4];
        #pragma unroll
        for (int f = 0; f < 8; f++)
            #pragma unroll
            for (int e = 0; e < 4; e++) s[f][e] = 0.f;
        #pragma unroll
        for (int ks = 0; ks < 4; ks++) {
            uint32_t kbh[8][2], kbl[8][2];
            #pragma unroll
            for (int p = 0; p < 4; p++) {
                int jrow = (p * 2 + (mm >> 1)) * 8 + mr;
                int dcol = ks * 16 + (mm & 1) * 8;
                uint32_t r0, r1, r2, r3;
                ldsm4(r0, r1, r2, r3, &Kh[jrow][dcol]);
                kbh[2*p][0] = r0; kbh[2*p][1] = r1; kbh[2*p+1][0] = r2; kbh[2*p+1][1] = r3;
                ldsm4(r0, r1, r2, r3, &Kl[jrow][dcol]);
                kbl[2*p][0] = r0; kbl[2*p][1] = r1; kbl[2*p+1][0] = r2; kbl[2*p+1][1] = r3;
            }
            #pragma unroll
            for (int f = 0; f < 8; f++) {
                mma_bf16(s[f][0], s[f][1], s[f][2], s[f][3],
                         qh[ks][0], qh[ks][1], qh[ks][2], qh[ks][3], kbh[f][0], kbh[f][1]);
                mma_bf16(s[f][0], s[f][1], s[f][2], s[f][3],
                         qh[ks][0], qh[ks][1], qh[ks][2], qh[ks][3], kbl[f][0], kbl[f][1]);
                mma_bf16(s[f][0], s[f][1], s[f][2], s[f][3],
                         ql[ks][0], ql[ks][1], ql[ks][2], ql[ks][3], kbh[f][0], kbh[f][1]);
            }
        }
        #pragma unroll
        for (int f = 0; f < 8; f++) {
            if (maskB[8 * f + 2 * tig])     { s[f][0] = -1e4f; s[f][2] = -1e4f; }
            if (maskB[8 * f + 2 * tig + 1]) { s[f][1] = -1e4f; s[f][3] = -1e4f; }
        }
        float mx0 = -1e30f, mx1 = -1e30f;
        #pragma unroll
        for (int f = 0; f < 8; f++) {
            mx0 = fmaxf(mx0, fmaxf(s[f][0], s[f][1]));
            mx1 = fmaxf(mx1, fmaxf(s[f][2], s[f][3]));
        }
        mx0 = fmaxf(mx0, __shfl_xor_sync(0xffffffffu, mx0, 1));
        mx0 = fmaxf(mx0, __shfl_xor_sync(0xffffffffu, mx0, 2));
        mx1 = fmaxf(mx1, __shfl_xor_sync(0xffffffffu, mx1, 1));
        mx1 = fmaxf(mx1, __shfl_xor_sync(0xffffffffu, mx1, 2));
        float mn0 = fmaxf(m0_, mx0), mn1 = fmaxf(m1_, mx1);
        float sc0 = __expf(m0_ - mn0), sc1 = __expf(m1_ - mn1);
        m0_ = mn0; m1_ = mn1;
        float sum0 = 0.f, sum1 = 0.f;
        #pragma unroll
        for (int f = 0; f < 8; f++) {
            s[f][0] = __expf(s[f][0] - mn0);
            s[f][1] = __expf(s[f][1] - mn0);
            s[f][2] = __expf(s[f][2] - mn1);
            s[f][3] = __expf(s[f][3] - mn1);
            sum0 += s[f][0] + s[f][1];
            sum1 += s[f][2] + s[f][3];
        }
        sum0 += __shfl_xor_sync(0xffffffffu, sum0, 1);
        sum0 += __shfl_xor_sync(0xffffffffu, sum0, 2);
        sum1 += __shfl_xor_sync(0xffffffffu, sum1, 1);
        sum1 += __shfl_xor_sync(0xffffffffu, sum1, 2);
        l0_ = l0_ * sc0 + sum0;
        l1_ = l1_ * sc1 + sum1;
        #pragma unroll
        for (int f = 0; f < 8; f++) {
            o[f][0] *= sc0; o[f][1] *= sc0;
            o[f][2] *= sc1; o[f][3] *= sc1;
        }
        #pragma unroll
        for (int kg = 0; kg < 4; kg++) {
            uint32_t ph[4], pl[4];
            split2(s[2*kg][0],   s[2*kg][1],   ph[0], pl[0]);
            split2(s[2*kg][2],   s[2*kg][3],   ph[1], pl[1]);
            split2(s[2*kg+1][0], s[2*kg+1][1], ph[2], pl[2]);
            split2(s[2*kg+1][2], s[2*kg+1][3], ph[3], pl[3]);
            uint32_t vbh[8][2], vbl[8][2];
            #pragma unroll
            for (int p = 0; p < 4; p++) {
                int jrow = kg * 16 + (mm & 1) * 8 + mr;
                int dcol = (p * 2 + (mm >> 1)) * 8;
                uint32_t r0, r1, r2, r3;
                ldsm4t(r0, r1, r2, r3, &Vh[jrow][dcol]);
                vbh[2*p][0] = r0; vbh[2*p][1] = r1; vbh[2*p+1][0] = r2; vbh[2*p+1][1] = r3;
                ldsm4t(r0, r1, r2, r3, &Vl[jrow][dcol]);
                vbl[2*p][0] = r0; vbl[2*p][1] = r1; vbl[2*p+1][0] = r2; vbl[2*p+1][1] = r3;
            }
            #pragma unroll
            for (int f = 0; f < 8; f++) {
                mma_bf16(o[f][0], o[f][1], o[f][2], o[f][3],
                         ph[0], ph[1], ph[2], ph[3], vbh[f][0], vbh[f][1]);
                mma_bf16(o[f][0], o[f][1], o[f][2], o[f][3],
                         ph[0], ph[1], ph[2], ph[3], vbl[f][0], vbl[f][1]);
                mma_bf16(o[f][0], o[f][1], o[f][2], o[f][3],
                         pl[0], pl[1], pl[2], pl[3], vbh[f][0], vbh[f][1]);
            }
        }
        __syncthreads();   // all reads of this stage done
        if (jt + 2 < 16) prefetch(jt + 2, buf);
    }

    float inv0 = 1.0f / l0_, inv1 = 1.0f / l1_;
    int i_loc = 16 * wrp + gid;
    #pragma unroll
    for (int f = 0; f < 8; f++) {
        int col = n * DH + 8 * f + 2 * tig;
        size_t row0 = ((size_t)(i0 + i_loc) * BB + b);
        size_t row1 = ((size_t)(i0 + i_loc + 8) * BB + b);
        uint32_t hp, lp;
        split2(o[f][0] * inv0, o[f][1] * inv0, hp, lp);
        *reinterpret_cast<uint32_t*>(&g_attn_h[row0 * NDH + col]) = hp;
        *reinterpret_cast<uint32_t*>(&g_attn_l[row0 * NDH + col]) = lp;
        split2(o[f][2] * inv1, o[f][3] * inv1, hp, lp);
        *reinterpret_cast<uint32_t*>(&g_attn_h[row1 * NDH + col]) = hp;
        *reinterpret_cast<uint32_t*>(&g_attn_l[row1 * NDH + col]) = lp;
    }
}

// ---------------- launch ----------------
extern "C" void kernel_launch(void* const* d_in, const int* in_sizes, int n_in,
                              void* d_out, int out_size) {
    const float* h     = (const float*)d_in[0];
    const float* c     = (const float*)d_in[1];
    const void*  mask  = d_in[2];
    const float* Wq    = (const float*)d_in[3];
    const float* Wkv   = (const float*)d_in[4];
    const float* Wo    = (const float*)d_in[5];
    const float* gamma = (const float*)d_in[6];
    const float* beta  = (const float*)d_in[7];
    float* out = (float*)d_out;

    const int smemG = 3 * STG_ELEMS * 2;   // 113664 B
    const int smemA = 2 * STGA * 2;        // 73728 B
    (void)cudaFuncSetAttribute(gemm_proj, cudaFuncAttributeMaxDynamicSharedMemorySize, smemG);
    (void)cudaFuncSetAttribute(gemm_out,  cudaFuncAttributeMaxDynamicSharedMemorySize, smemG);
    (void)cudaFuncSetAttribute(attn_kernel, cudaFuncAttributeMaxDynamicSharedMemorySize, smemA);

    mask_kernel<<<1, 256>>>((const unsigned int*)mask, (const unsigned char*)mask);
    ln_kernel<<<ROWS, 256>>>(h, gamma, beta);

    __nv_bfloat16 *ch, *cl, *wqh, *wql, *wkvh, *wkvl, *woh, *wol;
    __nv_bfloat16 *hlh, *hll, *ath, *atl;
    cudaGetSymbolAddress((void**)&ch,  g_c_h);   cudaGetSymbolAddress((void**)&cl,  g_c_l);
    cudaGetSymbolAddress((void**)&wqh, g_wq_h);  cudaGetSymbolAddress((void**)&wql, g_wq_l);
    cudaGetSymbolAddress((void**)&wkvh,g_wkv_h); cudaGetSymbolAddress((void**)&wkvl,g_wkv_l);
    cudaGetSymbolAddress((void**)&woh, g_wo_h);  cudaGetSymbolAddress((void**)&wol, g_wo_l);
    cudaGetSymbolAddress((void**)&hlh, g_hln_h); cudaGetSymbolAddress((void**)&hll, g_hln_l);
    cudaGetSymbolAddress((void**)&ath, g_attn_h);cudaGetSymbolAddress((void**)&atl, g_attn_l);

    conv_split4<<<(N4_TOT + 255)/256, 256>>>(
        (const float4*)c, (const float4*)Wq, (const float4*)Wkv, (const float4*)Wo,
        (uint2*)ch,  (uint2*)cl,  (uint2*)wqh, (uint2*)wql,
        (uint2*)wkvh,(uint2*)wkvl,(uint2*)woh, (uint2*)wol);

    gemm_proj<<<dim3(24, 64), 256, smemG>>>(ch, cl, wkvh, wkvl, hlh, hll, wqh, wql);
    attn_kernel<<<dim3(8, 128), 256, smemA>>>();
    gemm_out<<<dim3(8, 64), 256, smemG>>>(ath, atl, woh, wol, out);
}

// round 13
// speedup vs baseline: 3.0861x; 1.1735x over previous
#include <cuda_runtime.h>
#include <cuda_fp16.h>
#include <math.h>
#include <stdint.h>

#define QL   1024
#define KVL  1024
#define BB   8
#define DM   1024
#define NH   16
#define DH   64
#define ROWS (QL*BB)     // 8192
#define NDH  (NH*DH)     // 1024

// ---------------- scratch (device globals) ----------------
__device__ __align__(16) float g_hln[ROWS*DM];          // LN(h) fp32 residual
__device__ __align__(16) __half g_hln_h[ROWS*DM];
__device__ __align__(16) __half g_hln_l[ROWS*DM];
__device__ __align__(16) __half g_c_h[ROWS*DM];
__device__ __align__(16) __half g_c_l[ROWS*DM];
__device__ __align__(16) __half g_wq_h[DM*NDH];         // weights: hi only (2-term)
__device__ __align__(16) __half g_wkv_h[DM*2*NDH];
__device__ __align__(16) __half g_wo_h[NDH*DM];
__device__ __align__(16) __half g_q_h[BB*NH*QL*DH];
__device__ __align__(16) __half g_q_l[BB*NH*QL*DH];
__device__ __align__(16) __half g_k_h[BB*NH*KVL*DH];
__device__ __align__(16) __half g_k_l[BB*NH*KVL*DH];
__device__ __align__(16) __half g_v_h[BB*NH*KVL*DH];
__device__ __align__(16) __half g_v_l[BB*NH*KVL*DH];
__device__ __align__(16) __half g_attn_h[ROWS*NDH];
__device__ __align__(16) __half g_attn_l[ROWS*NDH];
__device__ __align__(16) int g_maskT[BB*KVL];           // [b][j], 1 = masked

// ---------------- helpers ----------------
__device__ __forceinline__ void ldsm4(uint32_t &r0, uint32_t &r1, uint32_t &r2, uint32_t &r3,
                                      const void* p) {
    uint32_t a = (uint32_t)__cvta_generic_to_shared(p);
    asm volatile("ldmatrix.sync.aligned.m8n8.x4.shared.b16 {%0,%1,%2,%3},[%4];\n"
                 : "=r"(r0), "=r"(r1), "=r"(r2), "=r"(r3) : "r"(a));
}
__device__ __forceinline__ void ldsm4t(uint32_t &r0, uint32_t &r1, uint32_t &r2, uint32_t &r3,
                                       const void* p) {
    uint32_t a = (uint32_t)__cvta_generic_to_shared(p);
    asm volatile("ldmatrix.sync.aligned.m8n8.x4.trans.shared.b16 {%0,%1,%2,%3},[%4];\n"
                 : "=r"(r0), "=r"(r1), "=r"(r2), "=r"(r3) : "r"(a));
}
__device__ __forceinline__ void mma_h(float &c0, float &c1, float &c2, float &c3,
                                      uint32_t a0, uint32_t a1, uint32_t a2, uint32_t a3,
                                      uint32_t b0, uint32_t b1) {
    asm volatile(
        "mma.sync.aligned.m16n8k16.row.col.f32.f16.f16.f32 "
        "{%0,%1,%2,%3},{%4,%5,%6,%7},{%8,%9},{%0,%1,%2,%3};\n"
        : "+f"(c0), "+f"(c1), "+f"(c2), "+f"(c3)
        : "r"(a0), "r"(a1), "r"(a2), "r"(a3), "r"(b0), "r"(b1));
}
__device__ __forceinline__ uint32_t packh(__half x, __half y) {
    return ((uint32_t)__half_as_ushort(y) << 16) | (uint32_t)__half_as_ushort(x);
}
__device__ __forceinline__ void split2h(float x, float y, uint32_t &hi, uint32_t &lo) {
    __half hx = __float2half_rn(x), hy = __float2half_rn(y);
    __half lx = __float2half_rn(x - __half2float(hx));
    __half ly = __float2half_rn(y - __half2float(hy));
    hi = packh(hx, hy);
    lo = packh(lx, ly);
}
__device__ __forceinline__ void cpasync16s(uint32_t s, const void* g) {
    asm volatile("cp.async.cg.shared.global [%0],[%1],16;\n" :: "r"(s), "l"(g));
}
__device__ __forceinline__ void cp_commit() { asm volatile("cp.async.commit_group;\n"); }
template<int N> __device__ __forceinline__ void cp_wait() {
    asm volatile("cp.async.wait_group %0;\n" :: "n"(N));
}

// ---------------- merged pre-pass: fp32->fp16 split (c hi/lo, weights hi) + mask ----------------
#define N4_C   (ROWS*DM/4)
#define N4_WQ  (DM*NDH/4)
#define N4_WKV (DM*2*NDH/4)
#define N4_WO  (NDH*DM/4)
#define N4_TOT (N4_C + N4_WQ + N4_WKV + N4_WO)
#define NB_CONV ((N4_TOT + 255)/256)

__global__ void conv_split4(const float4* __restrict__ c,  const float4* __restrict__ wq,
                            const float4* __restrict__ wkv,const float4* __restrict__ wo,
                            uint2* __restrict__ ch,  uint2* __restrict__ cl,
                            uint2* __restrict__ wqh, uint2* __restrict__ wkvh,
                            uint2* __restrict__ woh,
                            const unsigned int* __restrict__ mw,
                            const unsigned char* __restrict__ mb) {
    int t = threadIdx.x;
    if (blockIdx.x == NB_CONV) {   // mask block
        __shared__ int s_w01, s_f01;
        if (t == 0) { s_w01 = 1; s_f01 = 1; }
        __syncthreads();
        int w01 = 1, f01 = 1;
        for (int i = t; i < 2048; i += 256) {
            unsigned int w = mw[i];
            if (w > 1u) w01 = 0;
            if (w != 0u && w != 0x3F800000u) f01 = 0;
        }
        if (!w01) atomicAnd(&s_w01, 0);
        if (!f01) atomicAnd(&s_f01, 0);
        __syncthreads();
        bool word_mode = (s_w01 != 0) || (s_f01 != 0);
        for (int e = t; e < KVL*BB; e += 256) {
            int j = e >> 3, b = e & 7;
            int v = word_mode ? (mw[e] != 0u) : (mb[e] != 0);
            g_maskT[b * KVL + j] = v;
        }
        return;
    }
    int i = blockIdx.x * 256 + t;
    if (i >= N4_TOT) return;
    if (i < N4_C) {
        float4 v = c[i];
        uint32_t h0, l0, h1, l1;
        split2h(v.x, v.y, h0, l0);
        split2h(v.z, v.w, h1, l1);
        ch[i] = make_uint2(h0, h1);
        cl[i] = make_uint2(l0, l1);
    } else {
        const float4* src; uint2* dh; int off;
        if (i < N4_C + N4_WQ)               { src = wq;  dh = wqh;  off = i - N4_C; }
        else if (i < N4_C + N4_WQ + N4_WKV) { src = wkv; dh = wkvh; off = i - N4_C - N4_WQ; }
        else                                { src = wo;  dh = woh;  off = i - N4_C - N4_WQ - N4_WKV; }
        float4 v = src[off];
        __half a = __float2half_rn(v.x), b = __float2half_rn(v.y);
        __half cc = __float2half_rn(v.z), d = __float2half_rn(v.w);
        dh[off] = make_uint2(packh(a, b), packh(cc, d));
    }
}

// ---------------- layernorm: fp32 residual + fp16 hi/lo ----------------
__global__ void ln_kernel(const float* __restrict__ h,
                          const float* __restrict__ gamma,
                          const float* __restrict__ beta) {
    int row = blockIdx.x;
    int t = threadIdx.x;
    const float4* hp = reinterpret_cast<const float4*>(h + (size_t)row * DM);
    float4 x = hp[t];
    float s  = x.x + x.y + x.z + x.w;
    float ss = x.x*x.x + x.y*x.y + x.z*x.z + x.w*x.w;
    #pragma unroll
    for (int off = 16; off; off >>= 1) {
        s  += __shfl_xor_sync(0xffffffffu, s,  off);
        ss += __shfl_xor_sync(0xffffffffu, ss, off);
    }
    __shared__ float sh_s[8], sh_ss[8];
    __shared__ float s_mu, s_rstd;
    if ((t & 31) == 0) { sh_s[t >> 5] = s; sh_ss[t >> 5] = ss; }
    __syncthreads();
    if (t == 0) {
        float S = 0.f, SS = 0.f;
        #pragma unroll
        for (int i = 0; i < 8; i++) { S += sh_s[i]; SS += sh_ss[i]; }
        float mu  = S / DM;
        float var = SS / DM - mu * mu;
        s_mu = mu;
        s_rstd = rsqrtf(var + 1e-5f);
    }
    __syncthreads();
    float mu = s_mu, r = s_rstd;
    const float4* gp = reinterpret_cast<const float4*>(gamma);
    const float4* bp = reinterpret_cast<const float4*>(beta);
    float4 g = gp[t], bt = bp[t];
    float4 o;
    o.x = (x.x - mu) * r * g.x + bt.x;
    o.y = (x.y - mu) * r * g.y + bt.y;
    o.z = (x.z - mu) * r * g.z + bt.z;
    o.w = (x.w - mu) * r * g.w + bt.w;
    size_t base = (size_t)row * DM + t * 4;
    *reinterpret_cast<float4*>(&g_hln[base]) = o;
    uint32_t h0, l0, h1, l1;
    split2h(o.x, o.y, h0, l0);
    split2h(o.z, o.w, h1, l1);
    *reinterpret_cast<uint2*>(&g_hln_h[base]) = make_uint2(h0, h1);
    *reinterpret_cast<uint2*>(&g_hln_l[base]) = make_uint2(l0, l1);
}

// ---------------- fp16 2-term GEMM core: (Ah+Al)@Bh, cp.async 3-stage ----------------
#define AS_STRIDE 40
#define BS_STRIDE 136
#define STG_ELEMS (128*AS_STRIDE*2 + 32*BS_STRIDE)   // 14592 fp16 per stage
#define OFF_AH 0
#define OFF_AL (128*AS_STRIDE)
#define OFF_BH (2*128*AS_STRIDE)

template<int MODE>
__device__ __forceinline__ void gemm_core(
    const __half* __restrict__ Ah_g, const __half* __restrict__ Al_g,
    const __half* __restrict__ Bh_g,
    float* __restrict__ out, int K, int N, int m0, int n0, __half* sm) {
    uint32_t smb = (uint32_t)__cvta_generic_to_shared(sm);

    int t = threadIdx.x;
    int lane = t & 31, wrp = t >> 5;
    int gid = lane >> 2, tig = lane & 3;
    int wm = wrp & 3, wn = wrp >> 2;
    int mm = lane >> 3, mr = lane & 7;

    int rA0 = t >> 2,          cA0 = t & 3;
    int rA1 = (t + 256) >> 2,  cA1 = (t + 256) & 3;
    int rB0 = t >> 4,          cB0 = t & 15;
    int rB1 = (t + 256) >> 4,  cB1 = (t + 256) & 15;

    auto issue = [&](int kt, int st) {
        uint32_t S = smb + st * STG_ELEMS * 2;
        size_t ga0 = (size_t)(m0 + rA0) * K + kt + cA0 * 8;
        size_t ga1 = (size_t)(m0 + rA1) * K + kt + cA1 * 8;
        cpasync16s(S + (OFF_AH + rA0 * AS_STRIDE + cA0 * 8) * 2, &Ah_g[ga0]);
        cpasync16s(S + (OFF_AH + rA1 * AS_STRIDE + cA1 * 8) * 2, &Ah_g[ga1]);
        cpasync16s(S + (OFF_AL + rA0 * AS_STRIDE + cA0 * 8) * 2, &Al_g[ga0]);
        cpasync16s(S + (OFF_AL + rA1 * AS_STRIDE + cA1 * 8) * 2, &Al_g[ga1]);
        size_t gb0 = (size_t)(kt + rB0) * N + n0 + cB0 * 8;
        size_t gb1 = (size_t)(kt + rB1) * N + n0 + cB1 * 8;
        cpasync16s(S + (OFF_BH + rB0 * BS_STRIDE + cB0 * 8) * 2, &Bh_g[gb0]);
        cpasync16s(S + (OFF_BH + rB1 * BS_STRIDE + cB1 * 8) * 2, &Bh_g[gb1]);
        cp_commit();
    };

    float acc[2][8][4];
    #pragma unroll
    for (int i = 0; i < 2; i++)
        #pragma unroll
        for (int f = 0; f < 8; f++)
            #pragma unroll
            for (int e = 0; e < 4; e++) acc[i][f][e] = 0.f;

    int NT = K >> 5;
    issue(0, 0);
    issue(32, 1);
    for (int it = 0; it < NT; it++) {
        int cur = it % 3;
        if (it + 2 < NT) { issue((it + 2) << 5, (it + 2) % 3); cp_wait<2>(); }
        else if (it + 1 < NT) cp_wait<1>();
        else cp_wait<0>();
        __syncthreads();

        __half (*Ah)[AS_STRIDE] =
            reinterpret_cast<__half(*)[AS_STRIDE]>(sm + cur * STG_ELEMS + OFF_AH);
        __half (*Al)[AS_STRIDE] =
            reinterpret_cast<__half(*)[AS_STRIDE]>(sm + cur * STG_ELEMS + OFF_AL);
        __half (*Bh)[BS_STRIDE] =
            reinterpret_cast<__half(*)[BS_STRIDE]>(sm + cur * STG_ELEMS + OFF_BH);

        #pragma unroll
        for (int kk = 0; kk < 32; kk += 16) {
            uint32_t ah[2][4], al[2][4];
            #pragma unroll
            for (int im = 0; im < 2; im++) {
                int row = 32 * wm + 16 * im + (mm & 1) * 8 + mr;
                int col = kk + (mm >> 1) * 8;
                ldsm4(ah[im][0], ah[im][1], ah[im][2], ah[im][3], &Ah[row][col]);
                ldsm4(al[im][0], al[im][1], al[im][2], al[im][3], &Al[row][col]);
            }
            uint32_t bh[8][2];
            #pragma unroll
            for (int p = 0; p < 4; p++) {
                int krow = kk + (mm & 1) * 8 + mr;
                int ncol = 64 * wn + p * 16 + (mm >> 1) * 8;
                uint32_t r0, r1, r2, r3;
                ldsm4t(r0, r1, r2, r3, &Bh[krow][ncol]);
                bh[2*p][0] = r0; bh[2*p][1] = r1; bh[2*p+1][0] = r2; bh[2*p+1][1] = r3;
            }
            #pragma unroll
            for (int im = 0; im < 2; im++)
                #pragma unroll
                for (int f = 0; f < 8; f++) {
                    mma_h(acc[im][f][0], acc[im][f][1], acc[im][f][2], acc[im][f][3],
                          ah[im][0], ah[im][1], ah[im][2], ah[im][3], bh[f][0], bh[f][1]);
                    mma_h(acc[im][f][0], acc[im][f][1], acc[im][f][2], acc[im][f][3],
                          al[im][0], al[im][1], al[im][2], al[im][3], bh[f][0], bh[f][1]);
                }
        }
        __syncthreads();
    }

    // epilogue
    #pragma unroll
    for (int im = 0; im < 2; im++) {
        #pragma unroll
        for (int f = 0; f < 8; f++) {
            int cb = n0 + 64 * wn + 8 * f + 2 * tig;
            #pragma unroll
            for (int half_ = 0; half_ < 2; half_++) {
                int r = m0 + 32 * wm + 16 * im + gid + half_ * 8;
                float v0 = acc[im][f][half_ * 2 + 0];
                float v1 = acc[im][f][half_ * 2 + 1];
                if (MODE == 0) {
                    v0 *= 0.125f; v1 *= 0.125f;
                    int ii = r >> 3, b = r & 7, n = cb >> 6, dh = cb & 63;
                    size_t base = (((size_t)(b * NH + n)) * QL + ii) * DH + dh;
                    uint32_t hp, lp; split2h(v0, v1, hp, lp);
                    *reinterpret_cast<uint32_t*>(&g_q_h[base]) = hp;
                    *reinterpret_cast<uint32_t*>(&g_q_l[base]) = lp;
                } else if (MODE == 1) {
                    int jj = r >> 3, b = r & 7;
                    uint32_t hp, lp; split2h(v0, v1, hp, lp);
                    if (cb < NDH) {
                        int n = cb >> 6, dh = cb & 63;
                        size_t base = (((size_t)(b * NH + n)) * KVL + jj) * DH + dh;
                        *reinterpret_cast<uint32_t*>(&g_k_h[base]) = hp;
                        *reinterpret_cast<uint32_t*>(&g_k_l[base]) = lp;
                    } else {
                        int c2 = cb - NDH, n = c2 >> 6, dh = c2 & 63;
                        size_t base = (((size_t)(b * NH + n)) * KVL + jj) * DH + dh;
                        *reinterpret_cast<uint32_t*>(&g_v_h[base]) = hp;
                        *reinterpret_cast<uint32_t*>(&g_v_l[base]) = lp;
                    }
                } else {
                    size_t o = (size_t)r * DM + cb;
                    out[o]     = g_hln[o]     + v0;
                    out[o + 1] = g_hln[o + 1] + v1;
                }
            }
        }
    }
}

// merged KV + Q projection: blockIdx.x < 16 -> KV tile, else Q tile
__global__ __launch_bounds__(256, 2)
void gemm_proj(const __half* __restrict__ ch,  const __half* __restrict__ cl,
               const __half* __restrict__ wkvh,
               const __half* __restrict__ hlh, const __half* __restrict__ hll,
               const __half* __restrict__ wqh) {
    extern __shared__ __half smh[];
    int m0 = blockIdx.y * 128;
    if (blockIdx.x < 16) {
        gemm_core<1>(ch, cl, wkvh, nullptr, DM, 2 * NDH, m0, blockIdx.x * 128, smh);
    } else {
        gemm_core<0>(hlh, hll, wqh, nullptr, DM, NDH, m0, (blockIdx.x - 16) * 128, smh);
    }
}

__global__ __launch_bounds__(256, 2)
void gemm_out(const __half* __restrict__ ath, const __half* __restrict__ atl,
              const __half* __restrict__ woh, float* __restrict__ out) {
    extern __shared__ __half smh[];
    gemm_core<2>(ath, atl, woh, out, NDH, DM, blockIdx.y * 128, blockIdx.x * 128, smh);
}

// ---------------- flash attention: fp16 3-term, cp.async double-buffered K/V ----------------
#define ATS 72
#define STGA (4*64*ATS)   // elems per stage = 18432
__global__ __launch_bounds__(256)
void attn_kernel() {
    extern __shared__ __half dynA[];
    __shared__ __align__(16) int maskSS[2][64];
    uint32_t sbA = (uint32_t)__cvta_generic_to_shared(dynA);
    uint32_t sbM = (uint32_t)__cvta_generic_to_shared(&maskSS[0][0]);

    int t = threadIdx.x;
    int lane = t & 31, wrp = t >> 5;
    int gid = lane >> 2, tig = lane & 3;
    int mm = lane >> 3, mr = lane & 7;
    int i0 = blockIdx.x * 128;
    int bn = blockIdx.y;
    int b = bn >> 4, n = bn & 15;

    const __half* Qgh = g_q_h + (size_t)bn * QL * DH;
    const __half* Qgl = g_q_l + (size_t)bn * QL * DH;
    const __half* Kgh = g_k_h + (size_t)bn * KVL * DH;
    const __half* Kgl = g_k_l + (size_t)bn * KVL * DH;
    const __half* Vgh = g_v_h + (size_t)bn * KVL * DH;
    const __half* Vgl = g_v_l + (size_t)bn * KVL * DH;

    // ---- Q phase ----
    {
        __half (*Qh)[ATS] = reinterpret_cast<__half(*)[ATS]>(dynA);
        __half (*Ql)[ATS] = reinterpret_cast<__half(*)[ATS]>(dynA + 128 * ATS);
        #pragma unroll
        for (int e = 0; e < 4; e++) {
            int lin = e * 256 + t;
            int row = lin >> 3, c8 = lin & 7;
            *reinterpret_cast<uint4*>(&Qh[row][c8 * 8]) =
                *reinterpret_cast<const uint4*>(&Qgh[(size_t)(i0 + row) * DH + c8 * 8]);
            *reinterpret_cast<uint4*>(&Ql[row][c8 * 8]) =
                *reinterpret_cast<const uint4*>(&Qgl[(size_t)(i0 + row) * DH + c8 * 8]);
        }
    }
    __syncthreads();
    uint32_t qh[4][4], ql[4][4];
    {
        __half (*Qh)[ATS] = reinterpret_cast<__half(*)[ATS]>(dynA);
        __half (*Ql)[ATS] = reinterpret_cast<__half(*)[ATS]>(dynA + 128 * ATS);
        #pragma unroll
        for (int ks = 0; ks < 4; ks++) {
            int row = 16 * wrp + (mm & 1) * 8 + mr;
            int col = ks * 16 + (mm >> 1) * 8;
            ldsm4(qh[ks][0], qh[ks][1], qh[ks][2], qh[ks][3], &Qh[row][col]);
            ldsm4(ql[ks][0], ql[ks][1], ql[ks][2], ql[ks][3], &Ql[row][col]);
        }
    }
    __syncthreads();

    int rKV = t >> 3, cKV = t & 7;
    int rKV1 = (t + 256) >> 3, cKV1 = (t + 256) & 7;
    auto prefetch = [&](int jt, int buf) {
        int j0 = jt * 64;
        uint32_t base = sbA + buf * STGA * 2;
        {
            size_t g = (size_t)(j0 + rKV) * DH + cKV * 8;
            uint32_t so = (rKV * ATS + cKV * 8) * 2;
            cpasync16s(base + so,              Kgh + g);
            cpasync16s(base + 64*ATS*2 + so,   Kgl + g);
            cpasync16s(base + 2*64*ATS*2 + so, Vgh + g);
            cpasync16s(base + 3*64*ATS*2 + so, Vgl + g);
        }
        {
            size_t g = (size_t)(j0 + rKV1) * DH + cKV1 * 8;
            uint32_t so = (rKV1 * ATS + cKV1 * 8) * 2;
            cpasync16s(base + so,              Kgh + g);
            cpasync16s(base + 64*ATS*2 + so,   Kgl + g);
            cpasync16s(base + 2*64*ATS*2 + so, Vgh + g);
            cpasync16s(base + 3*64*ATS*2 + so, Vgl + g);
        }
        if (t < 16)
            cpasync16s(sbM + buf * 256 + t * 16, &g_maskT[b * KVL + j0 + t * 4]);
        cp_commit();
    };

    float m0_ = -1e30f, m1_ = -1e30f, l0_ = 0.f, l1_ = 0.f;
    float o[8][4];
    #pragma unroll
    for (int f = 0; f < 8; f++)
        #pragma unroll
        for (int e = 0; e < 4; e++) o[f][e] = 0.f;

    prefetch(0, 0);
    prefetch(1, 1);
    for (int jt = 0; jt < 16; jt++) {
        int buf = jt & 1;
        if (jt < 15) cp_wait<1>(); else cp_wait<0>();
        __syncthreads();

        __half (*Kh)[ATS] = reinterpret_cast<__half(*)[ATS]>(dynA + buf * STGA);
        __half (*Kl)[ATS] = reinterpret_cast<__half(*)[ATS]>(dynA + buf * STGA + 64 * ATS);
        __half (*Vh)[ATS] = reinterpret_cast<__half(*)[ATS]>(dynA + buf * STGA + 2 * 64 * ATS);
        __half (*Vl)[ATS] = reinterpret_cast<__half(*)[ATS]>(dynA + buf * STGA + 3 * 64 * ATS);
        const int* maskB = maskSS[buf];

        float s[8][4];
        #pragma unroll
        for (int f = 0; f < 8; f++)
            #pragma unroll
            for (int e = 0; e < 4; e++) s[f][e] = 0.f;
        #pragma unroll
        for (int ks = 0; ks < 4; ks++) {
            uint32_t kbh[8][2], kbl[8][2];
            #pragma unroll
            for (int p = 0; p < 4; p++) {
                int jrow = (p * 2 + (mm >> 1)) * 8 + mr;
                int dcol = ks * 16 + (mm & 1) * 8;
                uint32_t r0, r1, r2, r3;
                ldsm4(r0, r1, r2, r3, &Kh[jrow][dcol]);
                kbh[2*p][0] = r0; kbh[2*p][1] = r1; kbh[2*p+1][0] = r2; kbh[2*p+1][1] = r3;
                ldsm4(r0, r1, r2, r3, &Kl[jrow][dcol]);
                kbl[2*p][0] = r0; kbl[2*p][1] = r1; kbl[2*p+1][0] = r2; kbl[2*p+1][1] = r3;
            }
            #pragma unroll
            for (int f = 0; f < 8; f++) {
                mma_h(s[f][0], s[f][1], s[f][2], s[f][3],
                      qh[ks][0], qh[ks][1], qh[ks][2], qh[ks][3], kbh[f][0], kbh[f][1]);
                mma_h(s[f][0], s[f][1], s[f][2], s[f][3],
                      qh[ks][0], qh[ks][1], qh[ks][2], qh[ks][3], kbl[f][0], kbl[f][1]);
                mma_h(s[f][0], s[f][1], s[f][2], s[f][3],
                      ql[ks][0], ql[ks][1], ql[ks][2], ql[ks][3], kbh[f][0], kbh[f][1]);
            }
        }
        #pragma unroll
        for (int f = 0; f < 8; f++) {
            if (maskB[8 * f + 2 * tig])     { s[f][0] = -1e4f; s[f][2] = -1e4f; }
            if (maskB[8 * f + 2 * tig + 1]) { s[f][1] = -1e4f; s[f][3] = -1e4f; }
        }
        float mx0 = -1e30f, mx1 = -1e30f;
        #pragma unroll
        for (int f = 0; f < 8; f++) {
            mx0 = fmaxf(mx0, fmaxf(s[f][0], s[f][1]));
            mx1 = fmaxf(mx1, fmaxf(s[f][2], s[f][3]));
        }
        mx0 = fmaxf(mx0, __shfl_xor_sync(0xffffffffu, mx0, 1));
        mx0 = fmaxf(mx0, __shfl_xor_sync(0xffffffffu, mx0, 2));
        mx1 = fmaxf(mx1, __shfl_xor_sync(0xffffffffu, mx1, 1));
        mx1 = fmaxf(mx1, __shfl_xor_sync(0xffffffffu, mx1, 2));
        float mn0 = fmaxf(m0_, mx0), mn1 = fmaxf(m1_, mx1);
        float sc0 = __expf(m0_ - mn0), sc1 = __expf(m1_ - mn1);
        m0_ = mn0; m1_ = mn1;
        float sum0 = 0.f, sum1 = 0.f;
        #pragma unroll
        for (int f = 0; f < 8; f++) {
            s[f][0] = __expf(s[f][0] - mn0);
            s[f][1] = __expf(s[f][1] - mn0);
            s[f][2] = __expf(s[f][2] - mn1);
            s[f][3] = __expf(s[f][3] - mn1);
            sum0 += s[f][0] + s[f][1];
            sum1 += s[f][2] + s[f][3];
        }
        sum0 += __shfl_xor_sync(0xffffffffu, sum0, 1);
        sum0 += __shfl_xor_sync(0xffffffffu, sum0, 2);
        sum1 += __shfl_xor_sync(0xffffffffu, sum1, 1);
        sum1 += __shfl_xor_sync(0xffffffffu, sum1, 2);
        l0_ = l0_ * sc0 + sum0;
        l1_ = l1_ * sc1 + sum1;
        #pragma unroll
        for (int f = 0; f < 8; f++) {
            o[f][0] *= sc0; o[f][1] *= sc0;
            o[f][2] *= sc1; o[f][3] *= sc1;
        }
        #pragma unroll
        for (int kg = 0; kg < 4; kg++) {
            uint32_t ph[4], pl[4];
            split2h(s[2*kg][0],   s[2*kg][1],   ph[0], pl[0]);
            split2h(s[2*kg][2],   s[2*kg][3],   ph[1], pl[1]);
            split2h(s[2*kg+1][0], s[2*kg+1][1], ph[2], pl[2]);
            split2h(s[2*kg+1][2], s[2*kg+1][3], ph[3], pl[3]);
            uint32_t vbh[8][2], vbl[8][2];
            #pragma unroll
            for (int p = 0; p < 4; p++) {
                int jrow = kg * 16 + (mm & 1) * 8 + mr;
                int dcol = (p * 2 + (mm >> 1)) * 8;
                uint32_t r0, r1, r2, r3;
                ldsm4t(r0, r1, r2, r3, &Vh[jrow][dcol]);
                vbh[2*p][0] = r0; vbh[2*p][1] = r1; vbh[2*p+1][0] = r2; vbh[2*p+1][1] = r3;
                ldsm4t(r0, r1, r2, r3, &Vl[jrow][dcol]);
                vbl[2*p][0] = r0; vbl[2*p][1] = r1; vbl[2*p+1][0] = r2; vbl[2*p+1][1] = r3;
            }
            #pragma unroll
            for (int f = 0; f < 8; f++) {
                mma_h(o[f][0], o[f][1], o[f][2], o[f][3],
                      ph[0], ph[1], ph[2], ph[3], vbh[f][0], vbh[f][1]);
                mma_h(o[f][0], o[f][1], o[f][2], o[f][3],
                      ph[0], ph[1], ph[2], ph[3], vbl[f][0], vbl[f][1]);
                mma_h(o[f][0], o[f][1], o[f][2], o[f][3],
                      pl[0], pl[1], pl[2], pl[3], vbh[f][0], vbh[f][1]);
            }
        }
        __syncthreads();
        if (jt + 2 < 16) prefetch(jt + 2, buf);
    }

    float inv0 = 1.0f / l0_, inv1 = 1.0f / l1_;
    int i_loc = 16 * wrp + gid;
    #pragma unroll
    for (int f = 0; f < 8; f++) {
        int col = n * DH + 8 * f + 2 * tig;
        size_t row0 = ((size_t)(i0 + i_loc) * BB + b);
        size_t row1 = ((size_t)(i0 + i_loc + 8) * BB + b);
        uint32_t hp, lp;
        split2h(o[f][0] * inv0, o[f][1] * inv0, hp, lp);
        *reinterpret_cast<uint32_t*>(&g_attn_h[row0 * NDH + col]) = hp;
        *reinterpret_cast<uint32_t*>(&g_attn_l[row0 * NDH + col]) = lp;
        split2h(o[f][2] * inv1, o[f][3] * inv1, hp, lp);
        *reinterpret_cast<uint32_t*>(&g_attn_h[row1 * NDH + col]) = hp;
        *reinterpret_cast<uint32_t*>(&g_attn_l[row1 * NDH + col]) = lp;
    }
}

// ---------------- launch ----------------
extern "C" void kernel_launch(void* const* d_in, const int* in_sizes, int n_in,
                              void* d_out, int out_size) {
    const float* h     = (const float*)d_in[0];
    const float* c     = (const float*)d_in[1];
    const void*  mask  = d_in[2];
    const float* Wq    = (const float*)d_in[3];
    const float* Wkv   = (const float*)d_in[4];
    const float* Wo    = (const float*)d_in[5];
    const float* gamma = (const float*)d_in[6];
    const float* beta  = (const float*)d_in[7];
    float* out = (float*)d_out;

    const int smemG = 3 * STG_ELEMS * 2;   // 87552 B
    const int smemA = 2 * STGA * 2;        // 73728 B
    (void)cudaFuncSetAttribute(gemm_proj, cudaFuncAttributeMaxDynamicSharedMemorySize, smemG);
    (void)cudaFuncSetAttribute(gemm_out,  cudaFuncAttributeMaxDynamicSharedMemorySize, smemG);
    (void)cudaFuncSetAttribute(attn_kernel, cudaFuncAttributeMaxDynamicSharedMemorySize, smemA);

    __half *ch, *cl, *wqh, *wkvh, *woh, *hlh, *hll, *ath, *atl;
    cudaGetSymbolAddress((void**)&ch,  g_c_h);   cudaGetSymbolAddress((void**)&cl,  g_c_l);
    cudaGetSymbolAddress((void**)&wqh, g_wq_h);
    cudaGetSymbolAddress((void**)&wkvh,g_wkv_h);
    cudaGetSymbolAddress((void**)&woh, g_wo_h);
    cudaGetSymbolAddress((void**)&hlh, g_hln_h); cudaGetSymbolAddress((void**)&hll, g_hln_l);
    cudaGetSymbolAddress((void**)&ath, g_attn_h);cudaGetSymbolAddress((void**)&atl, g_attn_l);

    ln_kernel<<<ROWS, 256>>>(h, gamma, beta);
    conv_split4<<<NB_CONV + 1, 256>>>(
        (const float4*)c, (const float4*)Wq, (const float4*)Wkv, (const float4*)Wo,
        (uint2*)ch, (uint2*)cl, (uint2*)wqh, (uint2*)wkvh, (uint2*)woh,
        (const unsigned int*)mask, (const unsigned char*)mask);

    gemm_proj<<<dim3(24, 64), 256, smemG>>>(ch, cl, wkvh, hlh, hll, wqh);
    attn_kernel<<<dim3(8, 128), 256, smemA>>>();
    gemm_out<<<dim3(8, 64), 256, smemG>>>(ath, atl, woh, out);
}